// round 10
// baseline (speedup 1.0000x reference)
#include <cuda_runtime.h>
#include <cuda_bf16.h>
#include <cstdint>
#include <mma.h>
using namespace nvcuda;

#define BB 16
#define CC 1024
#define PP 512
#define NN 4096
#define MM 1024
typedef __nv_bfloat16 bf16;

// ---- scratch (device globals; ALWAYS resolved via cudaGetSymbolAddress) ----
__device__ __align__(16) bf16  g_xb [(long)BB*CC*NN];
__device__ __align__(16) float g_ixf[(long)BB*CC*MM];
__device__ __align__(16) bf16  g_ixb[(long)BB*CC*MM];
__device__ __align__(16) bf16  g_qT [(long)BB*NN*PP];
__device__ __align__(16) bf16  g_k  [(long)BB*PP*MM];
__device__ __align__(16) bf16  g_vT [(long)BB*MM*PP];
__device__ __align__(16) float g_S  [(long)BB*NN*MM];
__device__ __align__(16) bf16  g_P  [(long)BB*NN*MM];
__device__ __align__(16) bf16  g_oT [(long)BB*NN*PP];
__device__ __align__(16) bf16  g_wqb[PP*CC];
__device__ __align__(16) bf16  g_wkb[PP*CC];
__device__ __align__(16) bf16  g_wvb[PP*CC];
__device__ __align__(16) bf16  g_woutT[PP*CC];
__device__ float g_xsum [BB*CC];
__device__ float g_ixsum[BB*CC];
__device__ float g_qmn[BB*PP];
__device__ float g_kmn[BB*PP];
__device__ float g_mask[BB*MM];
__device__ float g_t[BB*CC];
__device__ float g_gc[BB*PP];
__device__ float g_gcw[BB*CC];

// ---------------- elementwise / reductions ----------------

__global__ void k_f2bf(const float* __restrict__ src, bf16* __restrict__ dst, long n4){
    long i = (long)blockIdx.x*256 + threadIdx.x;
    if (i >= n4) return;
    float4 f = ((const float4*)src)[i];
    ((__nv_bfloat162*)dst)[i*2]   = __floats2bfloat162_rn(f.x, f.y);
    ((__nv_bfloat162*)dst)[i*2+1] = __floats2bfloat162_rn(f.z, f.w);
}

__global__ void k_zero2(float* __restrict__ a, float* __restrict__ b){
    int idx = blockIdx.x*256 + threadIdx.x;          // grid 128: 64 blocks each
    if (blockIdx.x < 64) a[idx] = 0.f;
    else b[idx - 16384] = 0.f;
}

// pool + accumulate per-(b,c) sums of x (over n) and pooled ix (over m)
__global__ void k_pool2(const float* __restrict__ x, float* __restrict__ ixf,
                        bf16* __restrict__ ixb, float* __restrict__ xsum,
                        float* __restrict__ ixsum){
    long idx = (long)blockIdx.x*256 + threadIdx.x;   // B*C*M threads; block shares (b,c)
    int m = (int)(idx & (MM-1));
    long bc = idx >> 10;
    int hk = m >> 5, wk = m & 31;
    const float* base = x + bc*(long)NN + (hk*2)*64 + wk*2;
    float a = base[0], bq = base[1], c = base[64], d = base[65];
    float v = fmaxf(fmaxf(a, bq), fmaxf(c, d));
    ixf[idx] = v;
    ixb[idx] = __float2bfloat16(v);
    float s4 = (a + bq) + (c + d);
    __shared__ float r1[256], r2[256];
    int tid = threadIdx.x;
    r1[tid] = s4; r2[tid] = v; __syncthreads();
    for (int st=128; st; st>>=1){
        if (tid < st){ r1[tid]+=r1[tid+st]; r2[tid]+=r2[tid+st]; }
        __syncthreads();
    }
    if (tid == 0){ atomicAdd(&xsum[bc], r1[0]); atomicAdd(&ixsum[bc], r2[0]); }
}

// qmn[b][p] = (wq @ xsum_b)/NN ; kmn[b][p] = (wk @ ixsum_b)/MM   (bias cancels in whitening)
__global__ void k_means(const float* __restrict__ wq, const float* __restrict__ wk,
                        const float* __restrict__ xsum, const float* __restrict__ ixsum,
                        float* __restrict__ qmn, float* __restrict__ kmn){
    int p = blockIdx.x, b = blockIdx.y, tid = threadIdx.x;   // grid (512,16), block 256
    const float* xs = xsum + b*CC;
    const float* is = ixsum + b*CC;
    float sq = 0.f, sk = 0.f;
    for (int c=tid; c<CC; c+=256){
        sq += wq[p*CC+c]*xs[c];
        sk += wk[p*CC+c]*is[c];
    }
    __shared__ float r1[256], r2[256];
    r1[tid]=sq; r2[tid]=sk; __syncthreads();
    for (int st=128; st; st>>=1){
        if (tid<st){ r1[tid]+=r1[tid+st]; r2[tid]+=r2[tid+st]; }
        __syncthreads();
    }
    if (tid==0){ qmn[b*PP+p] = r1[0]*(1.f/NN); kmn[b*PP+p] = r2[0]*(1.f/MM); }
}

__global__ void k_wtrans(const float* __restrict__ w, bf16* __restrict__ wt){
    int idx = blockIdx.x*256 + threadIdx.x;          // P*C threads
    int p = idx >> 10, c = idx & 1023;
    wt[idx] = __float2bfloat16(w[c*PP + p]);
}

__global__ void k_softmax(const float* __restrict__ S, bf16* __restrict__ P){
    long r = blockIdx.x;                             // grid B*N, block 128
    const float* src = S + r*MM;
    bf16* dst = P + r*MM;
    int tid = threadIdx.x;
    __shared__ float red[128];
    float mx = -1e30f;
    #pragma unroll
    for (int i=0;i<8;i++) mx = fmaxf(mx, src[tid + i*128]);
    red[tid]=mx; __syncthreads();
    for (int st=64;st;st>>=1){ if (tid<st) red[tid]=fmaxf(red[tid],red[tid+st]); __syncthreads(); }
    mx = red[0]; __syncthreads();
    float e[8]; float s = 0.f;
    #pragma unroll
    for (int i=0;i<8;i++){ e[i] = __expf(src[tid + i*128] - mx); s += e[i]; }
    red[tid]=s; __syncthreads();
    for (int st=64;st;st>>=1){ if (tid<st) red[tid]+=red[tid+st]; __syncthreads(); }
    float rinv = 1.f/red[0];
    #pragma unroll
    for (int i=0;i<8;i++) dst[tid + i*128] = __float2bfloat16(e[i]*rinv);
}

// ---- f32 global-context branch ----
__global__ void k_masklogit(const float* __restrict__ ixf, const float* __restrict__ wmask,
                            const float* __restrict__ bmask, float* __restrict__ mask){
    int m = blockIdx.x*256 + threadIdx.x;            // grid (4,16)
    int b = blockIdx.y;
    const float* ix = ixf + (long)b*CC*MM;
    float s = bmask[0];
    for (int c=0;c<CC;c++) s += wmask[c]*ix[(long)c*MM + m];
    mask[b*MM+m] = s;
}

__global__ void k_masksoftmax(float* __restrict__ mask){  // grid (16), block 256
    int b = blockIdx.x; int tid = threadIdx.x;
    float* row = mask + b*MM;
    __shared__ float red[256];
    float mx = -1e30f;
    for (int m=tid;m<MM;m+=256) mx = fmaxf(mx, row[m]);
    red[tid]=mx; __syncthreads();
    for (int st=128;st;st>>=1){ if (tid<st) red[tid]=fmaxf(red[tid],red[tid+st]); __syncthreads(); }
    mx = red[0]; __syncthreads();
    float s = 0.f;
    for (int m=tid;m<MM;m+=256){ float e = __expf(row[m]-mx); row[m]=e; s+=e; }
    red[tid]=s; __syncthreads();
    for (int st=128;st;st>>=1){ if (tid<st) red[tid]+=red[tid+st]; __syncthreads(); }
    float rinv = 1.f/red[0];
    for (int m=tid;m<MM;m+=256) row[m] *= rinv;
}

__global__ void k_t(const float* __restrict__ ixf, const float* __restrict__ mask,
                    float* __restrict__ t){          // grid (1024,16), block 128
    int c = blockIdx.x, b = blockIdx.y, tid = threadIdx.x;
    const float* ix = ixf + ((long)b*CC + c)*MM;
    float s = 0.f;
    for (int m=tid;m<MM;m+=128) s += ix[m]*mask[b*MM+m];
    __shared__ float red[128];
    red[tid]=s; __syncthreads();
    for (int st=64;st;st>>=1){ if (tid<st) red[tid]+=red[tid+st]; __syncthreads(); }
    if (tid==0) t[b*CC+c] = red[0];
}

__global__ void k_gc(const float* __restrict__ wgc, const float* __restrict__ bgc,
                     const float* __restrict__ t, float* __restrict__ gc){
    int p = blockIdx.x, b = blockIdx.y, tid = threadIdx.x;   // grid (512,16), block 256
    float s = 0.f;
    for (int c=tid;c<CC;c+=256) s += wgc[p*CC+c]*t[b*CC+c];
    __shared__ float red[256];
    red[tid]=s; __syncthreads();
    for (int st=128;st;st>>=1){ if (tid<st) red[tid]+=red[tid+st]; __syncthreads(); }
    if (tid==0) gc[b*PP+p] = red[0] + bgc[p];
}

__global__ void k_gcw(const float* __restrict__ wout, const float* __restrict__ beta,
                      const float* __restrict__ gc, float* __restrict__ gcw){
    int c = blockIdx.x, b = blockIdx.y, tid = threadIdx.x;   // grid (1024,16), block 128
    float s = 0.f;
    for (int p=tid;p<PP;p+=128) s += wout[c*PP+p]*gc[b*PP+p];
    __shared__ float red[128];
    red[tid]=s; __syncthreads();
    for (int st=64;st;st>>=1){ if (tid<st) red[tid]+=red[tid+st]; __syncthreads(); }
    if (tid==0) gcw[b*CC+c] = beta[0]*red[0];
}

// ---- bf16 wmma GEMM, 128x128 tile, 8 warps, 2-stage cp.async pipeline ----
// MODE 1: bf16 Out[n*Mdim+m] = acc + bias[m]                      (v conv)
// MODE 2: f32  Out[n*Mdim+m] = xres + gamma[0]*acc + gcw[b*CC+n]  (final)
// MODE 3: f32  Out[m*Ndim+n] = acc * hscale                       (S)
// MODE 4: bf16 Out[m*Ndim+n] = acc                                (O)
// MODE 5: bf16 Out[n*Mdim+m] = acc - bias[b*PP+m]                 (q whiten)
// MODE 6: bf16 Out[m*Ndim+n] = acc - bias[b*PP+m]                 (k whiten)
#define LDA_ 40
#define LDB_ 136
struct SmemLd { bf16 A[2][128*LDA_]; bf16 B[2][32*LDB_]; };
union SmemU { SmemLd ld; float stage[64*136]; };

__device__ __forceinline__ void cp16(void* dst_smem, const void* src_gmem){
    unsigned int d = (unsigned int)__cvta_generic_to_shared(dst_smem);
    asm volatile("cp.async.cg.shared.global [%0], [%1], 16;\n" :: "r"(d), "l"(src_gmem));
}

template<int MODE>
__global__ void __launch_bounds__(256)
gemm_kernel(const bf16* __restrict__ A, const bf16* __restrict__ Bmat,
            const float* __restrict__ bias, void* __restrict__ OutV,
            int Mdim, int Ndim, int Kdim, long sA, long sB, long sOut,
            const float* __restrict__ xres, const float* __restrict__ gcw,
            const float* __restrict__ gamma, float hscale)
{
    __shared__ __align__(16) SmemU sm;
    const int b = blockIdx.z;
    A    += (long)b * sA;
    Bmat += (long)b * sB;
    const int m0 = blockIdx.y * 128;
    const int n0 = blockIdx.x * 128;
    const int tid = threadIdx.x;
    const int wid = tid >> 5;
    const int warp_m = wid >> 2;
    const int warp_n = wid & 3;

    wmma::fragment<wmma::accumulator,16,16,16,float> acc[4][2];
    #pragma unroll
    for (int i=0;i<4;i++)
        #pragma unroll
        for (int j=0;j<2;j++) wmma::fill_fragment(acc[i][j], 0.f);

    auto load_tiles = [&](int st, int k0){
        #pragma unroll
        for (int p=0;p<2;p++){
            int ch = tid + p*256;                        // A tile 128x32 = 512 16B chunks
            int r = ch >> 2, c8 = (ch & 3)*8;
            cp16(&sm.ld.A[st][r*LDA_ + c8], &A[(long)(m0+r)*Kdim + k0 + c8]);
        }
        #pragma unroll
        for (int p=0;p<2;p++){
            int ch = tid + p*256;                        // B tile 32x128 = 512 chunks
            int r = ch >> 4, c8 = (ch & 15)*8;
            cp16(&sm.ld.B[st][r*LDB_ + c8], &Bmat[(long)(k0+r)*Ndim + n0 + c8]);
        }
    };

    load_tiles(0, 0);
    asm volatile("cp.async.commit_group;\n");

    int stg = 0;
    for (int k0 = 0; k0 < Kdim; k0 += 32) {
        const bool hasnext = (k0 + 32 < Kdim);
        if (hasnext){
            load_tiles(stg^1, k0+32);
            asm volatile("cp.async.commit_group;\n");
            asm volatile("cp.async.wait_group 1;\n");
        } else {
            asm volatile("cp.async.wait_group 0;\n");
        }
        __syncthreads();
        #pragma unroll
        for (int kk=0; kk<32; kk+=16){
            wmma::fragment<wmma::matrix_a,16,16,16,bf16,wmma::row_major> af[4];
            wmma::fragment<wmma::matrix_b,16,16,16,bf16,wmma::row_major> bfr[2];
            #pragma unroll
            for (int i=0;i<4;i++)
                wmma::load_matrix_sync(af[i], &sm.ld.A[stg][(warp_m*64 + i*16)*LDA_ + kk], LDA_);
            #pragma unroll
            for (int j=0;j<2;j++)
                wmma::load_matrix_sync(bfr[j], &sm.ld.B[stg][kk*LDB_ + warp_n*32 + j*16], LDB_);
            #pragma unroll
            for (int i=0;i<4;i++)
                #pragma unroll
                for (int j=0;j<2;j++)
                    wmma::mma_sync(acc[i][j], af[i], bfr[j], acc[i][j]);
        }
        __syncthreads();
        stg ^= 1;
    }

    const float gmul = (MODE==2) ? gamma[0] : 0.f;
    for (int h=0; h<2; h++){
        if (warp_m == h){
            #pragma unroll
            for (int i=0;i<4;i++)
                #pragma unroll
                for (int j=0;j<2;j++)
                    wmma::store_matrix_sync(&sm.stage[(i*16)*136 + warp_n*32 + j*16],
                                            acc[i][j], 136, wmma::mem_row_major);
        }
        __syncthreads();
        if (MODE == 4){
            bf16* Out = (bf16*)OutV + (long)b*sOut;
            for (int it=0; it<32; it++){
                int idx = it*256 + tid;
                int r = idx >> 7, c = idx & 127;
                int gmi = m0 + h*64 + r, gni = n0 + c;
                Out[(long)gmi*Ndim + gni] = __float2bfloat16(sm.stage[r*136 + c]);
            }
        } else if (MODE == 6){
            bf16* Out = (bf16*)OutV + (long)b*sOut;
            for (int it=0; it<32; it++){
                int idx = it*256 + tid;
                int r = idx >> 7, c = idx & 127;
                int gmi = m0 + h*64 + r, gni = n0 + c;
                Out[(long)gmi*Ndim + gni] = __float2bfloat16(sm.stage[r*136 + c] - bias[b*PP + gmi]);
            }
        } else if (MODE == 1 || MODE == 5){
            bf16* Out = (bf16*)OutV + (long)b*sOut;
            for (int it=0; it<32; it++){
                int idx = it*256 + tid;
                int r = idx & 63, c = idx >> 6;
                int gmi = m0 + h*64 + r, gni = n0 + c;
                float bv = (MODE==1) ? bias[gmi] : -bias[b*PP + gmi];
                Out[(long)gni*Mdim + gmi] = __float2bfloat16(sm.stage[r*136 + c] + bv);
            }
        } else if (MODE == 2){
            float* Out = (float*)OutV + (long)b*sOut;
            const float* xr = xres + (long)b*sOut;
            for (int it=0; it<32; it++){
                int idx = it*256 + tid;
                int r = idx & 63, c = idx >> 6;
                int gmi = m0 + h*64 + r;
                int gni = n0 + c;
                long o = (long)gni*Mdim + gmi;
                Out[o] = xr[o] + gmul*sm.stage[r*136 + c] + gcw[b*CC + gni];
            }
        } else {  // MODE 3
            float* Out = (float*)OutV + (long)b*sOut;
            for (int it=0; it<32; it++){
                int idx = it*256 + tid;
                int r = idx >> 7, c = idx & 127;
                int gmi = m0 + h*64 + r, gni = n0 + c;
                Out[(long)gmi*Ndim + gni] = sm.stage[r*136 + c] * hscale;
            }
        }
        __syncthreads();
    }
}

extern "C" void kernel_launch(void* const* d_in, const int* in_sizes, int n_in,
                              void* d_out, int out_size) {
    const float* x     = (const float*)d_in[0];
    const float* wq    = (const float*)d_in[1];
    const float* wk    = (const float*)d_in[3];
    const float* wv    = (const float*)d_in[5];
    const float* bv    = (const float*)d_in[6];
    const float* wgc   = (const float*)d_in[7];
    const float* bgc   = (const float*)d_in[8];
    const float* wmask = (const float*)d_in[9];
    const float* bmask = (const float*)d_in[10];
    const float* wout  = (const float*)d_in[11];
    const float* gamma = (const float*)d_in[12];
    const float* beta  = (const float*)d_in[13];

    void *p_xb, *p_ixf, *p_ixb, *p_qT, *p_k, *p_vT, *p_S, *p_P, *p_oT;
    void *p_wqb, *p_wkb, *p_wvb, *p_woutT, *p_mask, *p_t, *p_gc, *p_gcw;
    void *p_xsum, *p_ixsum, *p_qmn, *p_kmn;
    cudaGetSymbolAddress(&p_xb,  g_xb);
    cudaGetSymbolAddress(&p_ixf, g_ixf);
    cudaGetSymbolAddress(&p_ixb, g_ixb);
    cudaGetSymbolAddress(&p_qT,  g_qT);
    cudaGetSymbolAddress(&p_k,   g_k);
    cudaGetSymbolAddress(&p_vT,  g_vT);
    cudaGetSymbolAddress(&p_S,   g_S);
    cudaGetSymbolAddress(&p_P,   g_P);
    cudaGetSymbolAddress(&p_oT,  g_oT);
    cudaGetSymbolAddress(&p_wqb, g_wqb);
    cudaGetSymbolAddress(&p_wkb, g_wkb);
    cudaGetSymbolAddress(&p_wvb, g_wvb);
    cudaGetSymbolAddress(&p_woutT, g_woutT);
    cudaGetSymbolAddress(&p_mask, g_mask);
    cudaGetSymbolAddress(&p_t,   g_t);
    cudaGetSymbolAddress(&p_gc,  g_gc);
    cudaGetSymbolAddress(&p_gcw, g_gcw);
    cudaGetSymbolAddress(&p_xsum, g_xsum);
    cudaGetSymbolAddress(&p_ixsum, g_ixsum);
    cudaGetSymbolAddress(&p_qmn, g_qmn);
    cudaGetSymbolAddress(&p_kmn, g_kmn);

    const float SINV = 0.8838834764831844f;  // 1/(sqrt(512)*0.05)

    // 1..5, then the big q GEMM is launch #6 (ncu -s 5 -c 1 profiles it)
    k_f2bf<<<65536, 256>>>(x, (bf16*)p_xb, (long)BB*CC*NN/4);                       // 1
    k_zero2<<<128, 256>>>((float*)p_xsum, (float*)p_ixsum);                         // 2
    k_pool2<<<65536, 256>>>(x, (float*)p_ixf, (bf16*)p_ixb,
                            (float*)p_xsum, (float*)p_ixsum);                       // 3
    k_means<<<dim3(512,16), 256>>>(wq, wk, (const float*)p_xsum,
                                   (const float*)p_ixsum, (float*)p_qmn, (float*)p_kmn); // 4
    k_f2bf<<<512, 256>>>(wq, (bf16*)p_wqb, PP*CC/4);                                // 5

    // q = whiten(wq@x) -> qT [b][n][p]                                             // 6 (profiled)
    gemm_kernel<5><<<dim3(32,4,16), 256>>>((const bf16*)p_wqb, (const bf16*)p_xb,
        (const float*)p_qmn, p_qT,
        PP, NN, CC, 0, (long)CC*NN, (long)NN*PP, nullptr, nullptr, nullptr, 0.f);

    k_f2bf<<<512, 256>>>(wk, (bf16*)p_wkb, PP*CC/4);
    // k = whiten(wk@ix) -> k [b][p][m]
    gemm_kernel<6><<<dim3(8,4,16), 256>>>((const bf16*)p_wkb, (const bf16*)p_ixb,
        (const float*)p_kmn, p_k,
        PP, MM, CC, 0, (long)CC*MM, (long)PP*MM, nullptr, nullptr, nullptr, 0.f);

    k_f2bf<<<512, 256>>>(wv, (bf16*)p_wvb, PP*CC/4);
    // v = wv@ix + bv -> vT [b][m][p]
    gemm_kernel<1><<<dim3(8,4,16), 256>>>((const bf16*)p_wvb, (const bf16*)p_ixb, bv, p_vT,
        PP, MM, CC, 0, (long)CC*MM, (long)MM*PP, nullptr, nullptr, nullptr, 0.f);

    // S = (qT @ k) * SINV -> f32 [b][n][m]
    gemm_kernel<3><<<dim3(8,32,16), 256>>>((const bf16*)p_qT, (const bf16*)p_k, nullptr, p_S,
        NN, MM, PP, (long)NN*PP, (long)PP*MM, (long)NN*MM, nullptr, nullptr, nullptr, SINV);

    // softmax -> P bf16
    k_softmax<<<BB*NN, 128>>>((const float*)p_S, (bf16*)p_P);

    // O = P @ vT -> oT bf16 [b][n][p]
    gemm_kernel<4><<<dim3(4,32,16), 256>>>((const bf16*)p_P, (const bf16*)p_vT, nullptr, p_oT,
        NN, PP, MM, (long)NN*MM, (long)MM*PP, (long)NN*PP, nullptr, nullptr, nullptr, 0.f);

    // global-context branch (vgc conv eliminated: gc = wgc@(ix@mask)+bgc)
    k_masklogit<<<dim3(4,16), 256>>>((const float*)p_ixf, wmask, bmask, (float*)p_mask);
    k_masksoftmax<<<16, 256>>>((float*)p_mask);
    k_t<<<dim3(1024,16), 128>>>((const float*)p_ixf, (const float*)p_mask, (float*)p_t);
    k_gc<<<dim3(512,16), 256>>>(wgc, bgc, (const float*)p_t, (float*)p_gc);
    k_gcw<<<dim3(1024,16), 128>>>(wout, beta, (const float*)p_gc, (float*)p_gcw);
    k_wtrans<<<2048, 256>>>(wout, (bf16*)p_woutT);

    // out[b][c][n] = x + gamma*(oT @ woutT)^T + gcw
    gemm_kernel<2><<<dim3(8,32,16), 256>>>((const bf16*)p_oT, (const bf16*)p_woutT, nullptr, d_out,
        NN, CC, PP, (long)NN*PP, 0, (long)CC*NN, x, (const float*)p_gcw, gamma, 0.f);
}

// round 11
// speedup vs baseline: 1.0504x; 1.0504x over previous
#include <cuda_runtime.h>
#include <cuda_bf16.h>
#include <cstdint>
#include <mma.h>
using namespace nvcuda;

#define BB 16
#define CC 1024
#define PP 512
#define NN 4096
#define MM 1024
typedef __nv_bfloat16 bf16;

// ---- scratch (device globals; ALWAYS resolved via cudaGetSymbolAddress) ----
__device__ __align__(16) bf16  g_xb [(long)BB*CC*NN];
__device__ __align__(16) float g_ixf[(long)BB*CC*MM];
__device__ __align__(16) bf16  g_ixb[(long)BB*CC*MM];
__device__ __align__(16) bf16  g_qT [(long)BB*NN*PP];
__device__ __align__(16) bf16  g_k  [(long)BB*PP*MM];
__device__ __align__(16) bf16  g_vT [(long)BB*MM*PP];
__device__ __align__(16) bf16  g_Sb [(long)BB*NN*MM];
__device__ __align__(16) bf16  g_P  [(long)BB*NN*MM];
__device__ __align__(16) bf16  g_oT [(long)BB*NN*PP];
__device__ __align__(16) bf16  g_wqb[PP*CC];
__device__ __align__(16) bf16  g_wkb[PP*CC];
__device__ __align__(16) bf16  g_wvb[PP*CC];
__device__ __align__(16) bf16  g_woutT[PP*CC];
__device__ float g_xsum [BB*CC];
__device__ float g_ixsum[BB*CC];
__device__ float g_qmn[BB*PP];
__device__ float g_kmn[BB*PP];
__device__ float g_mask[BB*MM];
__device__ float g_t[BB*CC];
__device__ float g_gc[BB*PP];
__device__ float g_gcw[BB*CC];

// ---------------- glue kernels ----------------

__global__ void k_f2bf(const float* __restrict__ src, bf16* __restrict__ dst, long n4){
    long i = (long)blockIdx.x*256 + threadIdx.x;
    if (i >= n4) return;
    float4 f = ((const float4*)src)[i];
    ((__nv_bfloat162*)dst)[i*2]   = __floats2bfloat162_rn(f.x, f.y);
    ((__nv_bfloat162*)dst)[i*2+1] = __floats2bfloat162_rn(f.z, f.w);
}

// one block per (b,c): pool 2x2, write per-(b,c) sums of x and pooled ix directly
__global__ void k_pool2(const float* __restrict__ x, float* __restrict__ ixf,
                        bf16* __restrict__ ixb, float* __restrict__ xsum,
                        float* __restrict__ ixsum){
    long bc = blockIdx.x;                    // 0..B*C-1
    int tid = threadIdx.x;
    const float* xr = x + bc*(long)NN;
    float s_x = 0.f, s_ix = 0.f;
    #pragma unroll
    for (int i=0;i<4;i++){
        int m = tid + i*256;                 // 0..1023
        int hk = m >> 5, wk = m & 31;
        const float* base = xr + hk*128 + wk*2;
        float a = base[0], b2 = base[1], c = base[64], d = base[65];
        float v = fmaxf(fmaxf(a, b2), fmaxf(c, d));
        ixf[bc*(long)MM + m] = v;
        ixb[bc*(long)MM + m] = __float2bfloat16(v);
        s_ix += v;
        s_x  += (a + b2) + (c + d);
    }
    __shared__ float r1[256], r2[256];
    r1[tid]=s_x; r2[tid]=s_ix; __syncthreads();
    for (int st=128; st; st>>=1){
        if (tid<st){ r1[tid]+=r1[tid+st]; r2[tid]+=r2[tid+st]; }
        __syncthreads();
    }
    if (tid==0){ xsum[bc] = r1[0]; ixsum[bc] = r2[0]; }
}

// grid (512, 18): roles 0..15 = per-batch means; 16 = weight bf16 rows; 17 = woutT row
__global__ void k_prep(const float* __restrict__ wq, const float* __restrict__ wk,
                       const float* __restrict__ wv, const float* __restrict__ wout,
                       const float* __restrict__ xsum, const float* __restrict__ ixsum,
                       float* __restrict__ qmn, float* __restrict__ kmn,
                       bf16* __restrict__ wqb, bf16* __restrict__ wkb,
                       bf16* __restrict__ wvb, bf16* __restrict__ woutT){
    int p = blockIdx.x, role = blockIdx.y, tid = threadIdx.x;
    if (role < 16){
        int b = role;
        const float* xs = xsum + b*CC;
        const float* is = ixsum + b*CC;
        float sq = 0.f, sk = 0.f;
        for (int c=tid; c<CC; c+=256){
            sq += wq[p*CC+c]*xs[c];
            sk += wk[p*CC+c]*is[c];
        }
        __shared__ float r1[256], r2[256];
        r1[tid]=sq; r2[tid]=sk; __syncthreads();
        for (int st=128; st; st>>=1){
            if (tid<st){ r1[tid]+=r1[tid+st]; r2[tid]+=r2[tid+st]; }
            __syncthreads();
        }
        if (tid==0){ qmn[b*PP+p] = r1[0]*(1.f/NN); kmn[b*PP+p] = r2[0]*(1.f/MM); }
    } else if (role == 16){
        #pragma unroll
        for (int i=0;i<4;i++){
            int c = tid + i*256;
            wqb[p*CC+c] = __float2bfloat16(wq[p*CC+c]);
            wkb[p*CC+c] = __float2bfloat16(wk[p*CC+c]);
            wvb[p*CC+c] = __float2bfloat16(wv[p*CC+c]);
        }
    } else {
        #pragma unroll
        for (int i=0;i<4;i++){
            int c = tid + i*256;
            woutT[p*CC+c] = __float2bfloat16(wout[c*PP+p]);
        }
    }
}

__global__ void k_softmax(const bf16* __restrict__ S, bf16* __restrict__ P){
    long r = blockIdx.x;                     // grid B*N, block 128
    const bf16* src = S + r*MM;
    bf16* dst = P + r*MM;
    int tid = threadIdx.x;
    __shared__ float red[128];
    float v[8];
    #pragma unroll
    for (int i=0;i<8;i++) v[i] = __bfloat162float(src[tid + i*128]);
    float mx = -1e30f;
    #pragma unroll
    for (int i=0;i<8;i++) mx = fmaxf(mx, v[i]);
    red[tid]=mx; __syncthreads();
    for (int st=64;st;st>>=1){ if (tid<st) red[tid]=fmaxf(red[tid],red[tid+st]); __syncthreads(); }
    mx = red[0]; __syncthreads();
    float s = 0.f;
    #pragma unroll
    for (int i=0;i<8;i++){ v[i] = __expf(v[i] - mx); s += v[i]; }
    red[tid]=s; __syncthreads();
    for (int st=64;st;st>>=1){ if (tid<st) red[tid]+=red[tid+st]; __syncthreads(); }
    float rinv = 1.f/red[0];
    #pragma unroll
    for (int i=0;i<8;i++) dst[tid + i*128] = __float2bfloat16(v[i]*rinv);
}

// ---- f32 global-context branch ----
__global__ void k_masklogit(const float* __restrict__ ixf, const float* __restrict__ wmask,
                            const float* __restrict__ bmask, float* __restrict__ mask){
    int m = blockIdx.x*256 + threadIdx.x;    // grid (4,16)
    int b = blockIdx.y;
    const float* ix = ixf + (long)b*CC*MM;
    float s = bmask[0];
    for (int c=0;c<CC;c++) s += wmask[c]*ix[(long)c*MM + m];
    mask[b*MM+m] = s;
}

__global__ void k_masksoftmax(float* __restrict__ mask){  // grid (16), block 256
    int b = blockIdx.x; int tid = threadIdx.x;
    float* row = mask + b*MM;
    __shared__ float red[256];
    float mx = -1e30f;
    for (int m=tid;m<MM;m+=256) mx = fmaxf(mx, row[m]);
    red[tid]=mx; __syncthreads();
    for (int st=128;st;st>>=1){ if (tid<st) red[tid]=fmaxf(red[tid],red[tid+st]); __syncthreads(); }
    mx = red[0]; __syncthreads();
    float s = 0.f;
    for (int m=tid;m<MM;m+=256){ float e = __expf(row[m]-mx); row[m]=e; s+=e; }
    red[tid]=s; __syncthreads();
    for (int st=128;st;st>>=1){ if (tid<st) red[tid]+=red[tid+st]; __syncthreads(); }
    float rinv = 1.f/red[0];
    for (int m=tid;m<MM;m+=256) row[m] *= rinv;
}

__global__ void k_t(const float* __restrict__ ixf, const float* __restrict__ mask,
                    float* __restrict__ t){  // grid (1024,16), block 128
    int c = blockIdx.x, b = blockIdx.y, tid = threadIdx.x;
    const float* ix = ixf + ((long)b*CC + c)*MM;
    float s = 0.f;
    for (int m=tid;m<MM;m+=128) s += ix[m]*mask[b*MM+m];
    __shared__ float red[128];
    red[tid]=s; __syncthreads();
    for (int st=64;st;st>>=1){ if (tid<st) red[tid]+=red[tid+st]; __syncthreads(); }
    if (tid==0) t[b*CC+c] = red[0];
}

__global__ void k_gc(const float* __restrict__ wgc, const float* __restrict__ bgc,
                     const float* __restrict__ t, float* __restrict__ gc){
    int p = blockIdx.x, b = blockIdx.y, tid = threadIdx.x;   // grid (512,16), block 256
    float s = 0.f;
    for (int c=tid;c<CC;c+=256) s += wgc[p*CC+c]*t[b*CC+c];
    __shared__ float red[256];
    red[tid]=s; __syncthreads();
    for (int st=128;st;st>>=1){ if (tid<st) red[tid]+=red[tid+st]; __syncthreads(); }
    if (tid==0) gc[b*PP+p] = red[0] + bgc[p];
}

__global__ void k_gcw(const float* __restrict__ wout, const float* __restrict__ beta,
                      const float* __restrict__ gc, float* __restrict__ gcw){
    int c = blockIdx.x, b = blockIdx.y, tid = threadIdx.x;   // grid (1024,16), block 128
    float s = 0.f;
    for (int p=tid;p<PP;p+=128) s += wout[c*PP+p]*gc[b*PP+p];
    __shared__ float red[128];
    red[tid]=s; __syncthreads();
    for (int st=64;st;st>>=1){ if (tid<st) red[tid]+=red[tid+st]; __syncthreads(); }
    if (tid==0) gcw[b*CC+c] = beta[0]*red[0];
}

// ---- bf16 wmma GEMM, 128x256 tile, 8 warps (2x4), 2-stage cp.async, dynamic smem ----
// MODE 1: bf16 Out[n*Mdim+m] = acc + bias[m]                      (v conv)
// MODE 2: f32  Out[n*Mdim+m] = xres + gamma[0]*acc + gcw[b*CC+n]  (final)
// MODE 4: bf16 Out[m*Ndim+n] = acc                                (O)
// MODE 5: bf16 Out[n*Mdim+m] = acc - bias[b*PP+m]                 (q whiten)
// MODE 6: bf16 Out[m*Ndim+n] = acc - bias[b*PP+m]                 (k whiten)
// MODE 7: bf16 Out[m*Ndim+n] = acc * hscale                       (S bf16)
#define LDA_  40      // A smem ld (bf16): 32 + 8 pad; 80B rows (16B-mult)
#define LDBW  264     // B smem ld (bf16): 256 + 8 pad; 528B rows (16B-mult)
#define LDST  264     // stage ld (f32)
#define A_ST_BYTES (128*LDA_*2)          // 10240
#define B_ST_BYTES (32*LDBW*2)           // 16896
#define DYN_SMEM   (64*LDST*4 > 2*(A_ST_BYTES+B_ST_BYTES) ? 64*LDST*4 : 2*(A_ST_BYTES+B_ST_BYTES))
// loads: 2*(10240+16896)=54272 ; stage: 64*264*4=67584 -> DYN_SMEM=67584

__device__ __forceinline__ void cp16(void* dst_smem, const void* src_gmem){
    unsigned int d = (unsigned int)__cvta_generic_to_shared(dst_smem);
    asm volatile("cp.async.cg.shared.global [%0], [%1], 16;\n" :: "r"(d), "l"(src_gmem));
}

template<int MODE>
__global__ void __launch_bounds__(256, 1)
gemm_kernel(const bf16* __restrict__ A, const bf16* __restrict__ Bmat,
            const float* __restrict__ bias, void* __restrict__ OutV,
            int Mdim, int Ndim, int Kdim, long sA, long sB, long sOut,
            const float* __restrict__ xres, const float* __restrict__ gcw,
            const float* __restrict__ gamma, float hscale)
{
    extern __shared__ char smraw[];
    bf16* Abuf = (bf16*)smraw;                               // [2][128*LDA_]
    bf16* Bbuf = (bf16*)(smraw + 2*A_ST_BYTES);              // [2][32*LDBW]
    float* stage = (float*)smraw;                            // epilogue reuse

    const int b = blockIdx.z;
    A    += (long)b * sA;
    Bmat += (long)b * sB;
    const int m0 = blockIdx.y * 128;
    const int n0 = blockIdx.x * 256;
    const int tid = threadIdx.x;
    const int wid = tid >> 5;
    const int warp_m = wid >> 2;      // 0..1 (64 rows each)
    const int warp_n = wid & 3;       // 0..3 (64 cols each)

    wmma::fragment<wmma::accumulator,16,16,16,float> acc[4][4];
    #pragma unroll
    for (int i=0;i<4;i++)
        #pragma unroll
        for (int j=0;j<4;j++) wmma::fill_fragment(acc[i][j], 0.f);

    auto load_tiles = [&](int st, int k0){
        #pragma unroll
        for (int p=0;p<2;p++){                               // A: 128x32 = 512 chunks
            int ch = tid + p*256;
            int r = ch >> 2, c8 = (ch & 3)*8;
            cp16(&Abuf[st*128*LDA_ + r*LDA_ + c8], &A[(long)(m0+r)*Kdim + k0 + c8]);
        }
        #pragma unroll
        for (int p=0;p<4;p++){                               // B: 32x256 = 1024 chunks
            int ch = tid + p*256;
            int r = ch >> 5, c8 = (ch & 31)*8;
            cp16(&Bbuf[st*32*LDBW + r*LDBW + c8], &Bmat[(long)(k0+r)*Ndim + n0 + c8]);
        }
    };

    load_tiles(0, 0);
    asm volatile("cp.async.commit_group;\n");

    int stg = 0;
    for (int k0 = 0; k0 < Kdim; k0 += 32) {
        if (k0 + 32 < Kdim){
            load_tiles(stg^1, k0+32);
            asm volatile("cp.async.commit_group;\n");
            asm volatile("cp.async.wait_group 1;\n");
        } else {
            asm volatile("cp.async.wait_group 0;\n");
        }
        __syncthreads();
        const bf16* Ab = &Abuf[stg*128*LDA_];
        const bf16* Bb = &Bbuf[stg*32*LDBW];
        #pragma unroll
        for (int kk=0; kk<32; kk+=16){
            wmma::fragment<wmma::matrix_a,16,16,16,bf16,wmma::row_major> af[4];
            wmma::fragment<wmma::matrix_b,16,16,16,bf16,wmma::row_major> bfr[4];
            #pragma unroll
            for (int i=0;i<4;i++)
                wmma::load_matrix_sync(af[i], &Ab[(warp_m*64 + i*16)*LDA_ + kk], LDA_);
            #pragma unroll
            for (int j=0;j<4;j++)
                wmma::load_matrix_sync(bfr[j], &Bb[kk*LDBW + warp_n*64 + j*16], LDBW);
            #pragma unroll
            for (int i=0;i<4;i++)
                #pragma unroll
                for (int j=0;j<4;j++)
                    wmma::mma_sync(acc[i][j], af[i], bfr[j], acc[i][j]);
        }
        __syncthreads();
        stg ^= 1;
    }

    const float gmul = (MODE==2) ? gamma[0] : 0.f;
    for (int h=0; h<2; h++){
        if (warp_m == h){
            #pragma unroll
            for (int i=0;i<4;i++)
                #pragma unroll
                for (int j=0;j<4;j++)
                    wmma::store_matrix_sync(&stage[(i*16)*LDST + warp_n*64 + j*16],
                                            acc[i][j], LDST, wmma::mem_row_major);
        }
        __syncthreads();
        if (MODE == 4 || MODE == 6 || MODE == 7){
            bf16* Out = (bf16*)OutV + (long)b*sOut;
            for (int it=0; it<64; it++){
                int idx = it*256 + tid;
                int r = idx >> 8, c = idx & 255;
                int gmi = m0 + h*64 + r, gni = n0 + c;
                float v = stage[r*LDST + c];
                if (MODE == 6) v -= bias[b*PP + gmi];
                if (MODE == 7) v *= hscale;
                Out[(long)gmi*Ndim + gni] = __float2bfloat16(v);
            }
        } else if (MODE == 1 || MODE == 5){
            bf16* Out = (bf16*)OutV + (long)b*sOut;
            for (int it=0; it<64; it++){
                int idx = it*256 + tid;
                int r = idx & 63, c = idx >> 6;
                int gmi = m0 + h*64 + r, gni = n0 + c;
                float bv = (MODE==1) ? bias[gmi] : -bias[b*PP + gmi];
                Out[(long)gni*Mdim + gmi] = __float2bfloat16(stage[r*LDST + c] + bv);
            }
        } else {  // MODE 2
            float* Out = (float*)OutV + (long)b*sOut;
            const float* xr = xres + (long)b*sOut;
            for (int it=0; it<64; it++){
                int idx = it*256 + tid;
                int r = idx & 63, c = idx >> 6;
                int gmi = m0 + h*64 + r;
                int gni = n0 + c;
                long o = (long)gni*Mdim + gmi;
                Out[o] = xr[o] + gmul*stage[r*LDST + c] + gcw[b*CC + gni];
            }
        }
        __syncthreads();
    }
}

extern "C" void kernel_launch(void* const* d_in, const int* in_sizes, int n_in,
                              void* d_out, int out_size) {
    const float* x     = (const float*)d_in[0];
    const float* wq    = (const float*)d_in[1];
    const float* wk    = (const float*)d_in[3];
    const float* wv    = (const float*)d_in[5];
    const float* bv    = (const float*)d_in[6];
    const float* wgc   = (const float*)d_in[7];
    const float* bgc   = (const float*)d_in[8];
    const float* wmask = (const float*)d_in[9];
    const float* bmask = (const float*)d_in[10];
    const float* wout  = (const float*)d_in[11];
    const float* gamma = (const float*)d_in[12];
    const float* beta  = (const float*)d_in[13];

    void *p_xb, *p_ixf, *p_ixb, *p_qT, *p_k, *p_vT, *p_Sb, *p_P, *p_oT;
    void *p_wqb, *p_wkb, *p_wvb, *p_woutT, *p_mask, *p_t, *p_gc, *p_gcw;
    void *p_xsum, *p_ixsum, *p_qmn, *p_kmn;
    cudaGetSymbolAddress(&p_xb,  g_xb);
    cudaGetSymbolAddress(&p_ixf, g_ixf);
    cudaGetSymbolAddress(&p_ixb, g_ixb);
    cudaGetSymbolAddress(&p_qT,  g_qT);
    cudaGetSymbolAddress(&p_k,   g_k);
    cudaGetSymbolAddress(&p_vT,  g_vT);
    cudaGetSymbolAddress(&p_Sb,  g_Sb);
    cudaGetSymbolAddress(&p_P,   g_P);
    cudaGetSymbolAddress(&p_oT,  g_oT);
    cudaGetSymbolAddress(&p_wqb, g_wqb);
    cudaGetSymbolAddress(&p_wkb, g_wkb);
    cudaGetSymbolAddress(&p_wvb, g_wvb);
    cudaGetSymbolAddress(&p_woutT, g_woutT);
    cudaGetSymbolAddress(&p_mask, g_mask);
    cudaGetSymbolAddress(&p_t,   g_t);
    cudaGetSymbolAddress(&p_gc,  g_gc);
    cudaGetSymbolAddress(&p_gcw, g_gcw);
    cudaGetSymbolAddress(&p_xsum, g_xsum);
    cudaGetSymbolAddress(&p_ixsum, g_ixsum);
    cudaGetSymbolAddress(&p_qmn, g_qmn);
    cudaGetSymbolAddress(&p_kmn, g_kmn);

    cudaFuncSetAttribute(gemm_kernel<1>, cudaFuncAttributeMaxDynamicSharedMemorySize, DYN_SMEM);
    cudaFuncSetAttribute(gemm_kernel<2>, cudaFuncAttributeMaxDynamicSharedMemorySize, DYN_SMEM);
    cudaFuncSetAttribute(gemm_kernel<4>, cudaFuncAttributeMaxDynamicSharedMemorySize, DYN_SMEM);
    cudaFuncSetAttribute(gemm_kernel<5>, cudaFuncAttributeMaxDynamicSharedMemorySize, DYN_SMEM);
    cudaFuncSetAttribute(gemm_kernel<6>, cudaFuncAttributeMaxDynamicSharedMemorySize, DYN_SMEM);
    cudaFuncSetAttribute(gemm_kernel<7>, cudaFuncAttributeMaxDynamicSharedMemorySize, DYN_SMEM);

    const float SINV = 0.8838834764831844f;  // 1/(sqrt(512)*0.05)

    // launches: 1..3 prep, then #4..#7 are the big GEMMs (ncu capture lands on one)
    k_f2bf<<<65536, 256>>>(x, (bf16*)p_xb, (long)BB*CC*NN/4);                       // 1
    k_pool2<<<BB*CC, 256>>>(x, (float*)p_ixf, (bf16*)p_ixb,
                            (float*)p_xsum, (float*)p_ixsum);                       // 2
    k_prep<<<dim3(512,18), 256>>>(wq, wk, wv, wout,
        (const float*)p_xsum, (const float*)p_ixsum,
        (float*)p_qmn, (float*)p_kmn,
        (bf16*)p_wqb, (bf16*)p_wkb, (bf16*)p_wvb, (bf16*)p_woutT);                  // 3

    // q = whiten(wq@x) -> qT [b][n][p]                                             // 4
    gemm_kernel<5><<<dim3(16,4,16), 256, DYN_SMEM>>>((const bf16*)p_wqb, (const bf16*)p_xb,
        (const float*)p_qmn, p_qT,
        PP, NN, CC, 0, (long)CC*NN, (long)NN*PP, nullptr, nullptr, nullptr, 0.f);

    // k = whiten(wk@ix) -> k [b][p][m]                                             // 5
    gemm_kernel<6><<<dim3(4,4,16), 256, DYN_SMEM>>>((const bf16*)p_wkb, (const bf16*)p_ixb,
        (const float*)p_kmn, p_k,
        PP, MM, CC, 0, (long)CC*MM, (long)PP*MM, nullptr, nullptr, nullptr, 0.f);

    // v = wv@ix + bv -> vT [b][m][p]                                               // 6
    gemm_kernel<1><<<dim3(4,4,16), 256, DYN_SMEM>>>((const bf16*)p_wvb, (const bf16*)p_ixb,
        bv, p_vT,
        PP, MM, CC, 0, (long)CC*MM, (long)MM*PP, nullptr, nullptr, nullptr, 0.f);

    // S = (qT @ k) * SINV -> bf16 [b][n][m]                                        // 7
    gemm_kernel<7><<<dim3(4,32,16), 256, DYN_SMEM>>>((const bf16*)p_qT, (const bf16*)p_k,
        nullptr, p_Sb,
        NN, MM, PP, (long)NN*PP, (long)PP*MM, (long)NN*MM, nullptr, nullptr, nullptr, SINV);

    // softmax -> P bf16
    k_softmax<<<BB*NN, 128>>>((const bf16*)p_Sb, (bf16*)p_P);

    // O = P @ vT -> oT bf16 [b][n][p]
    gemm_kernel<4><<<dim3(2,32,16), 256, DYN_SMEM>>>((const bf16*)p_P, (const bf16*)p_vT,
        nullptr, p_oT,
        NN, PP, MM, (long)NN*MM, (long)MM*PP, (long)NN*PP, nullptr, nullptr, nullptr, 0.f);

    // global-context branch (vgc conv eliminated: gc = wgc@(ix@mask)+bgc)
    k_masklogit<<<dim3(4,16), 256>>>((const float*)p_ixf, wmask, bmask, (float*)p_mask);
    k_masksoftmax<<<16, 256>>>((float*)p_mask);
    k_t<<<dim3(1024,16), 128>>>((const float*)p_ixf, (const float*)p_mask, (float*)p_t);
    k_gc<<<dim3(512,16), 256>>>(wgc, bgc, (const float*)p_t, (float*)p_gc);
    k_gcw<<<dim3(1024,16), 128>>>(wout, beta, (const float*)p_gc, (float*)p_gcw);

    // out[b][c][n] = x + gamma*(oT @ woutT)^T + gcw
    gemm_kernel<2><<<dim3(4,32,16), 256, DYN_SMEM>>>((const bf16*)p_oT, (const bf16*)p_woutT,
        nullptr, d_out,
        NN, CC, PP, (long)NN*PP, 0, (long)CC*NN, x, (const float*)p_gcw, gamma, 0.f);
}

// round 12
// speedup vs baseline: 1.1110x; 1.0577x over previous
#include <cuda_runtime.h>
#include <cuda_bf16.h>
#include <cstdint>
#include <mma.h>
using namespace nvcuda;

#define BB 16
#define CC 1024
#define PP 512
#define NN 4096
#define MM 1024
typedef __nv_bfloat16 bf16;

// ---- scratch (device globals; ALWAYS resolved via cudaGetSymbolAddress) ----
__device__ __align__(16) bf16  g_xb [(long)BB*CC*NN];
__device__ __align__(16) float g_ixf[(long)BB*CC*MM];
__device__ __align__(16) bf16  g_ixb[(long)BB*CC*MM];
__device__ __align__(16) bf16  g_qT [(long)BB*NN*PP];
__device__ __align__(16) bf16  g_k  [(long)BB*PP*MM];
__device__ __align__(16) bf16  g_vT [(long)BB*MM*PP];
__device__ __align__(16) bf16  g_Sb [(long)BB*NN*MM];
__device__ __align__(16) bf16  g_P  [(long)BB*NN*MM];
__device__ __align__(16) bf16  g_oT [(long)BB*NN*PP];
__device__ __align__(16) bf16  g_wqb[PP*CC];
__device__ __align__(16) bf16  g_wkb[PP*CC];
__device__ __align__(16) bf16  g_wvb[PP*CC];
__device__ __align__(16) bf16  g_woutT[PP*CC];
__device__ float g_xsum [BB*CC];
__device__ float g_ixsum[BB*CC];
__device__ float g_qmn[BB*PP];
__device__ float g_kmn[BB*PP];
__device__ float g_mask[BB*MM];
__device__ float g_t[BB*CC];
__device__ float g_gc[BB*PP];
__device__ float g_gcw[BB*CC];

// ---------------- glue kernels ----------------

__global__ void k_f2bf(const float* __restrict__ src, bf16* __restrict__ dst, long n4){
    long i = (long)blockIdx.x*256 + threadIdx.x;
    if (i >= n4) return;
    float4 f = ((const float4*)src)[i];
    ((__nv_bfloat162*)dst)[i*2]   = __floats2bfloat162_rn(f.x, f.y);
    ((__nv_bfloat162*)dst)[i*2+1] = __floats2bfloat162_rn(f.z, f.w);
}

__global__ void k_pool2(const float* __restrict__ x, float* __restrict__ ixf,
                        bf16* __restrict__ ixb, float* __restrict__ xsum,
                        float* __restrict__ ixsum){
    long bc = blockIdx.x;                    // 0..B*C-1
    int tid = threadIdx.x;
    const float* xr = x + bc*(long)NN;
    float s_x = 0.f, s_ix = 0.f;
    #pragma unroll
    for (int i=0;i<4;i++){
        int m = tid + i*256;
        int hk = m >> 5, wk = m & 31;
        const float* base = xr + hk*128 + wk*2;
        float a = base[0], b2 = base[1], c = base[64], d = base[65];
        float v = fmaxf(fmaxf(a, b2), fmaxf(c, d));
        ixf[bc*(long)MM + m] = v;
        ixb[bc*(long)MM + m] = __float2bfloat16(v);
        s_ix += v;
        s_x  += (a + b2) + (c + d);
    }
    __shared__ float r1[256], r2[256];
    r1[tid]=s_x; r2[tid]=s_ix; __syncthreads();
    for (int st=128; st; st>>=1){
        if (tid<st){ r1[tid]+=r1[tid+st]; r2[tid]+=r2[tid+st]; }
        __syncthreads();
    }
    if (tid==0){ xsum[bc] = r1[0]; ixsum[bc] = r2[0]; }
}

__global__ void k_prep(const float* __restrict__ wq, const float* __restrict__ wk,
                       const float* __restrict__ wv, const float* __restrict__ wout,
                       const float* __restrict__ xsum, const float* __restrict__ ixsum,
                       float* __restrict__ qmn, float* __restrict__ kmn,
                       bf16* __restrict__ wqb, bf16* __restrict__ wkb,
                       bf16* __restrict__ wvb, bf16* __restrict__ woutT){
    int p = blockIdx.x, role = blockIdx.y, tid = threadIdx.x;
    if (role < 16){
        int b = role;
        const float* xs = xsum + b*CC;
        const float* is = ixsum + b*CC;
        float sq = 0.f, sk = 0.f;
        for (int c=tid; c<CC; c+=256){
            sq += wq[p*CC+c]*xs[c];
            sk += wk[p*CC+c]*is[c];
        }
        __shared__ float r1[256], r2[256];
        r1[tid]=sq; r2[tid]=sk; __syncthreads();
        for (int st=128; st; st>>=1){
            if (tid<st){ r1[tid]+=r1[tid+st]; r2[tid]+=r2[tid+st]; }
            __syncthreads();
        }
        if (tid==0){ qmn[b*PP+p] = r1[0]*(1.f/NN); kmn[b*PP+p] = r2[0]*(1.f/MM); }
    } else if (role == 16){
        #pragma unroll
        for (int i=0;i<4;i++){
            int c = tid + i*256;
            wqb[p*CC+c] = __float2bfloat16(wq[p*CC+c]);
            wkb[p*CC+c] = __float2bfloat16(wk[p*CC+c]);
            wvb[p*CC+c] = __float2bfloat16(wv[p*CC+c]);
        }
    } else {
        #pragma unroll
        for (int i=0;i<4;i++){
            int c = tid + i*256;
            woutT[p*CC+c] = __float2bfloat16(wout[c*PP+p]);
        }
    }
}

__global__ void k_softmax(const bf16* __restrict__ S, bf16* __restrict__ P){
    long r = blockIdx.x;                     // grid B*N, block 128
    const bf16* src = S + r*MM;
    bf16* dst = P + r*MM;
    int tid = threadIdx.x;
    __shared__ float red[128];
    float v[8];
    #pragma unroll
    for (int i=0;i<8;i++) v[i] = __bfloat162float(src[tid + i*128]);
    float mx = -1e30f;
    #pragma unroll
    for (int i=0;i<8;i++) mx = fmaxf(mx, v[i]);
    red[tid]=mx; __syncthreads();
    for (int st=64;st;st>>=1){ if (tid<st) red[tid]=fmaxf(red[tid],red[tid+st]); __syncthreads(); }
    mx = red[0]; __syncthreads();
    float s = 0.f;
    #pragma unroll
    for (int i=0;i<8;i++){ v[i] = __expf(v[i] - mx); s += v[i]; }
    red[tid]=s; __syncthreads();
    for (int st=64;st;st>>=1){ if (tid<st) red[tid]+=red[tid+st]; __syncthreads(); }
    float rinv = 1.f/red[0];
    #pragma unroll
    for (int i=0;i<8;i++) dst[tid + i*128] = __float2bfloat16(v[i]*rinv);
}

// ---- f32 global-context branch ----
__global__ void k_masklogit(const float* __restrict__ ixf, const float* __restrict__ wmask,
                            const float* __restrict__ bmask, float* __restrict__ mask){
    int m = blockIdx.x*256 + threadIdx.x;    // grid (4,16)
    int b = blockIdx.y;
    const float* ix = ixf + (long)b*CC*MM;
    float s = bmask[0];
    for (int c=0;c<CC;c++) s += wmask[c]*ix[(long)c*MM + m];
    mask[b*MM+m] = s;
}

__global__ void k_masksoftmax(float* __restrict__ mask){  // grid (16), block 256
    int b = blockIdx.x; int tid = threadIdx.x;
    float* row = mask + b*MM;
    __shared__ float red[256];
    float mx = -1e30f;
    for (int m=tid;m<MM;m+=256) mx = fmaxf(mx, row[m]);
    red[tid]=mx; __syncthreads();
    for (int st=128;st;st>>=1){ if (tid<st) red[tid]=fmaxf(red[tid],red[tid+st]); __syncthreads(); }
    mx = red[0]; __syncthreads();
    float s = 0.f;
    for (int m=tid;m<MM;m+=256){ float e = __expf(row[m]-mx); row[m]=e; s+=e; }
    red[tid]=s; __syncthreads();
    for (int st=128;st;st>>=1){ if (tid<st) red[tid]+=red[tid+st]; __syncthreads(); }
    float rinv = 1.f/red[0];
    for (int m=tid;m<MM;m+=256) row[m] *= rinv;
}

__global__ void k_t(const float* __restrict__ ixf, const float* __restrict__ mask,
                    float* __restrict__ t){  // grid (1024,16), block 128
    int c = blockIdx.x, b = blockIdx.y, tid = threadIdx.x;
    const float* ix = ixf + ((long)b*CC + c)*MM;
    float s = 0.f;
    for (int m=tid;m<MM;m+=128) s += ix[m]*mask[b*MM+m];
    __shared__ float red[128];
    red[tid]=s; __syncthreads();
    for (int st=64;st;st>>=1){ if (tid<st) red[tid]+=red[tid+st]; __syncthreads(); }
    if (tid==0) t[b*CC+c] = red[0];
}

__global__ void k_gc(const float* __restrict__ wgc, const float* __restrict__ bgc,
                     const float* __restrict__ t, float* __restrict__ gc){
    int p = blockIdx.x, b = blockIdx.y, tid = threadIdx.x;   // grid (512,16), block 256
    float s = 0.f;
    for (int c=tid;c<CC;c+=256) s += wgc[p*CC+c]*t[b*CC+c];
    __shared__ float red[256];
    red[tid]=s; __syncthreads();
    for (int st=128;st;st>>=1){ if (tid<st) red[tid]+=red[tid+st]; __syncthreads(); }
    if (tid==0) gc[b*PP+p] = red[0] + bgc[p];
}

__global__ void k_gcw(const float* __restrict__ wout, const float* __restrict__ beta,
                      const float* __restrict__ gc, float* __restrict__ gcw){
    int c = blockIdx.x, b = blockIdx.y, tid = threadIdx.x;   // grid (1024,16), block 128
    float s = 0.f;
    for (int p=tid;p<PP;p+=128) s += wout[c*PP+p]*gc[b*PP+p];
    __shared__ float red[128];
    red[tid]=s; __syncthreads();
    for (int st=64;st;st>>=1){ if (tid<st) red[tid]+=red[tid+st]; __syncthreads(); }
    if (tid==0) gcw[b*CC+c] = beta[0]*red[0];
}

// ---- bf16 wmma GEMM, 128x256 tile, 8 warps, 3-stage cp.async, k-chunk 64, 1 sync/chunk ----
// MODE 1: bf16 Out[n*Mdim+m] = acc + bias[m]                      (v conv)
// MODE 2: f32  Out[n*Mdim+m] = xres + gamma[0]*acc + gcw[b*CC+n]  (final)
// MODE 4: bf16 Out[m*Ndim+n] = acc                                (O)
// MODE 5: bf16 Out[n*Mdim+m] = acc - bias[b*PP+m]                 (q whiten)
// MODE 6: bf16 Out[m*Ndim+n] = acc - bias[b*PP+m]                 (k whiten)
// MODE 7: bf16 Out[m*Ndim+n] = acc * hscale                       (S bf16)
#define KC    64
#define LDA_  72      // 64 + 8 pad (bf16); 144B rows
#define LDBW  264     // 256 + 8 pad (bf16); 528B rows
#define LDST  264     // stage ld (f32)
#define A_ST_ELE (128*LDA_)              // bf16 elements per A stage
#define B_ST_ELE (64*LDBW)
#define A_ST_BYTES (A_ST_ELE*2)          // 18432
#define B_ST_BYTES (B_ST_ELE*2)          // 33792
#define DYN_SMEM (3*(A_ST_BYTES+B_ST_BYTES))   // 156672 (> stage 67584)

__device__ __forceinline__ void cp16(void* dst_smem, const void* src_gmem){
    unsigned int d = (unsigned int)__cvta_generic_to_shared(dst_smem);
    asm volatile("cp.async.cg.shared.global [%0], [%1], 16;\n" :: "r"(d), "l"(src_gmem));
}

template<int MODE>
__global__ void __launch_bounds__(256, 1)
gemm_kernel(const bf16* __restrict__ A, const bf16* __restrict__ Bmat,
            const float* __restrict__ bias, void* __restrict__ OutV,
            int Mdim, int Ndim, int Kdim, long sA, long sB, long sOut,
            const float* __restrict__ xres, const float* __restrict__ gcw,
            const float* __restrict__ gamma, float hscale)
{
    extern __shared__ char smraw[];
    bf16* Abuf = (bf16*)smraw;                               // [3][A_ST_ELE]
    bf16* Bbuf = (bf16*)(smraw + 3*A_ST_BYTES);              // [3][B_ST_ELE]
    float* stage = (float*)smraw;                            // epilogue reuse

    const int b = blockIdx.z;
    A    += (long)b * sA;
    Bmat += (long)b * sB;
    const int m0 = blockIdx.y * 128;
    const int n0 = blockIdx.x * 256;
    const int tid = threadIdx.x;
    const int wid = tid >> 5;
    const int warp_m = wid >> 2;      // 0..1
    const int warp_n = wid & 3;       // 0..3

    wmma::fragment<wmma::accumulator,16,16,16,float> acc[4][4];
    #pragma unroll
    for (int i=0;i<4;i++)
        #pragma unroll
        for (int j=0;j<4;j++) wmma::fill_fragment(acc[i][j], 0.f);

    auto load_tiles = [&](int st, int k0){
        #pragma unroll
        for (int p=0;p<4;p++){                               // A: 128x64 = 1024 chunks
            int ch = tid + p*256;
            int r = ch >> 3, c8 = (ch & 7)*8;
            cp16(&Abuf[st*A_ST_ELE + r*LDA_ + c8], &A[(long)(m0+r)*Kdim + k0 + c8]);
        }
        #pragma unroll
        for (int p=0;p<8;p++){                               // B: 64x256 = 2048 chunks
            int ch = tid + p*256;
            int r = ch >> 5, c8 = (ch & 31)*8;
            cp16(&Bbuf[st*B_ST_ELE + r*LDBW + c8], &Bmat[(long)(k0+r)*Ndim + n0 + c8]);
        }
    };

    const int nk = Kdim / KC;
    load_tiles(0, 0);
    asm volatile("cp.async.commit_group;\n");
    load_tiles(1, KC);
    asm volatile("cp.async.commit_group;\n");

    for (int i = 0; i < nk; i++){
        asm volatile("cp.async.wait_group 1;\n");
        __syncthreads();
        if (i + 2 < nk) load_tiles((i+2)%3, (i+2)*KC);
        asm volatile("cp.async.commit_group;\n");

        const bf16* Ab = &Abuf[(i%3)*A_ST_ELE];
        const bf16* Bb = &Bbuf[(i%3)*B_ST_ELE];
        #pragma unroll
        for (int kk=0; kk<KC; kk+=16){
            wmma::fragment<wmma::matrix_a,16,16,16,bf16,wmma::row_major> af[4];
            wmma::fragment<wmma::matrix_b,16,16,16,bf16,wmma::row_major> bfr[4];
            #pragma unroll
            for (int ii=0;ii<4;ii++)
                wmma::load_matrix_sync(af[ii], &Ab[(warp_m*64 + ii*16)*LDA_ + kk], LDA_);
            #pragma unroll
            for (int j=0;j<4;j++)
                wmma::load_matrix_sync(bfr[j], &Bb[kk*LDBW + warp_n*64 + j*16], LDBW);
            #pragma unroll
            for (int ii=0;ii<4;ii++)
                #pragma unroll
                for (int j=0;j<4;j++)
                    wmma::mma_sync(acc[ii][j], af[ii], bfr[j], acc[ii][j]);
        }
    }
    asm volatile("cp.async.wait_group 0;\n");
    __syncthreads();

    const float gmul = (MODE==2) ? gamma[0] : 0.f;
    for (int h=0; h<2; h++){
        if (warp_m == h){
            #pragma unroll
            for (int i=0;i<4;i++)
                #pragma unroll
                for (int j=0;j<4;j++)
                    wmma::store_matrix_sync(&stage[(i*16)*LDST + warp_n*64 + j*16],
                                            acc[i][j], LDST, wmma::mem_row_major);
        }
        __syncthreads();
        if (MODE == 4 || MODE == 6 || MODE == 7){
            bf16* Out = (bf16*)OutV + (long)b*sOut;
            for (int it=0; it<64; it++){
                int idx = it*256 + tid;
                int r = idx >> 8, c = idx & 255;
                int gmi = m0 + h*64 + r, gni = n0 + c;
                float v = stage[r*LDST + c];
                if (MODE == 6) v -= bias[b*PP + gmi];
                if (MODE == 7) v *= hscale;
                Out[(long)gmi*Ndim + gni] = __float2bfloat16(v);
            }
        } else if (MODE == 1 || MODE == 5){
            bf16* Out = (bf16*)OutV + (long)b*sOut;
            for (int it=0; it<64; it++){
                int idx = it*256 + tid;
                int r = idx & 63, c = idx >> 6;
                int gmi = m0 + h*64 + r, gni = n0 + c;
                float bv = (MODE==1) ? bias[gmi] : -bias[b*PP + gmi];
                Out[(long)gni*Mdim + gmi] = __float2bfloat16(stage[r*LDST + c] + bv);
            }
        } else {  // MODE 2
            float* Out = (float*)OutV + (long)b*sOut;
            const float* xr = xres + (long)b*sOut;
            for (int it=0; it<64; it++){
                int idx = it*256 + tid;
                int r = idx & 63, c = idx >> 6;
                int gmi = m0 + h*64 + r;
                int gni = n0 + c;
                long o = (long)gni*Mdim + gmi;
                Out[o] = xr[o] + gmul*stage[r*LDST + c] + gcw[b*CC + gni];
            }
        }
        __syncthreads();
    }
}

extern "C" void kernel_launch(void* const* d_in, const int* in_sizes, int n_in,
                              void* d_out, int out_size) {
    const float* x     = (const float*)d_in[0];
    const float* wq    = (const float*)d_in[1];
    const float* wk    = (const float*)d_in[3];
    const float* wv    = (const float*)d_in[5];
    const float* bv    = (const float*)d_in[6];
    const float* wgc   = (const float*)d_in[7];
    const float* bgc   = (const float*)d_in[8];
    const float* wmask = (const float*)d_in[9];
    const float* bmask = (const float*)d_in[10];
    const float* wout  = (const float*)d_in[11];
    const float* gamma = (const float*)d_in[12];
    const float* beta  = (const float*)d_in[13];

    void *p_xb, *p_ixf, *p_ixb, *p_qT, *p_k, *p_vT, *p_Sb, *p_P, *p_oT;
    void *p_wqb, *p_wkb, *p_wvb, *p_woutT, *p_mask, *p_t, *p_gc, *p_gcw;
    void *p_xsum, *p_ixsum, *p_qmn, *p_kmn;
    cudaGetSymbolAddress(&p_xb,  g_xb);
    cudaGetSymbolAddress(&p_ixf, g_ixf);
    cudaGetSymbolAddress(&p_ixb, g_ixb);
    cudaGetSymbolAddress(&p_qT,  g_qT);
    cudaGetSymbolAddress(&p_k,   g_k);
    cudaGetSymbolAddress(&p_vT,  g_vT);
    cudaGetSymbolAddress(&p_Sb,  g_Sb);
    cudaGetSymbolAddress(&p_P,   g_P);
    cudaGetSymbolAddress(&p_oT,  g_oT);
    cudaGetSymbolAddress(&p_wqb, g_wqb);
    cudaGetSymbolAddress(&p_wkb, g_wkb);
    cudaGetSymbolAddress(&p_wvb, g_wvb);
    cudaGetSymbolAddress(&p_woutT, g_woutT);
    cudaGetSymbolAddress(&p_mask, g_mask);
    cudaGetSymbolAddress(&p_t,   g_t);
    cudaGetSymbolAddress(&p_gc,  g_gc);
    cudaGetSymbolAddress(&p_gcw, g_gcw);
    cudaGetSymbolAddress(&p_xsum, g_xsum);
    cudaGetSymbolAddress(&p_ixsum, g_ixsum);
    cudaGetSymbolAddress(&p_qmn, g_qmn);
    cudaGetSymbolAddress(&p_kmn, g_kmn);

    cudaFuncSetAttribute(gemm_kernel<1>, cudaFuncAttributeMaxDynamicSharedMemorySize, DYN_SMEM);
    cudaFuncSetAttribute(gemm_kernel<2>, cudaFuncAttributeMaxDynamicSharedMemorySize, DYN_SMEM);
    cudaFuncSetAttribute(gemm_kernel<4>, cudaFuncAttributeMaxDynamicSharedMemorySize, DYN_SMEM);
    cudaFuncSetAttribute(gemm_kernel<5>, cudaFuncAttributeMaxDynamicSharedMemorySize, DYN_SMEM);
    cudaFuncSetAttribute(gemm_kernel<6>, cudaFuncAttributeMaxDynamicSharedMemorySize, DYN_SMEM);
    cudaFuncSetAttribute(gemm_kernel<7>, cudaFuncAttributeMaxDynamicSharedMemorySize, DYN_SMEM);

    const float SINV = 0.8838834764831844f;  // 1/(sqrt(512)*0.05)

    // launches: 1..3 prep, then #4..#7 are the big GEMMs
    k_f2bf<<<65536, 256>>>(x, (bf16*)p_xb, (long)BB*CC*NN/4);                       // 1
    k_pool2<<<BB*CC, 256>>>(x, (float*)p_ixf, (bf16*)p_ixb,
                            (float*)p_xsum, (float*)p_ixsum);                       // 2
    k_prep<<<dim3(512,18), 256>>>(wq, wk, wv, wout,
        (const float*)p_xsum, (const float*)p_ixsum,
        (float*)p_qmn, (float*)p_kmn,
        (bf16*)p_wqb, (bf16*)p_wkb, (bf16*)p_wvb, (bf16*)p_woutT);                  // 3

    // q = whiten(wq@x) -> qT [b][n][p]                                             // 4
    gemm_kernel<5><<<dim3(16,4,16), 256, DYN_SMEM>>>((const bf16*)p_wqb, (const bf16*)p_xb,
        (const float*)p_qmn, p_qT,
        PP, NN, CC, 0, (long)CC*NN, (long)NN*PP, nullptr, nullptr, nullptr, 0.f);

    // k = whiten(wk@ix) -> k [b][p][m]                                             // 5
    gemm_kernel<6><<<dim3(4,4,16), 256, DYN_SMEM>>>((const bf16*)p_wkb, (const bf16*)p_ixb,
        (const float*)p_kmn, p_k,
        PP, MM, CC, 0, (long)CC*MM, (long)PP*MM, nullptr, nullptr, nullptr, 0.f);

    // v = wv@ix + bv -> vT [b][m][p]                                               // 6
    gemm_kernel<1><<<dim3(4,4,16), 256, DYN_SMEM>>>((const bf16*)p_wvb, (const bf16*)p_ixb,
        bv, p_vT,
        PP, MM, CC, 0, (long)CC*MM, (long)MM*PP, nullptr, nullptr, nullptr, 0.f);

    // S = (qT @ k) * SINV -> bf16 [b][n][m]                                        // 7
    gemm_kernel<7><<<dim3(4,32,16), 256, DYN_SMEM>>>((const bf16*)p_qT, (const bf16*)p_k,
        nullptr, p_Sb,
        NN, MM, PP, (long)NN*PP, (long)PP*MM, (long)NN*MM, nullptr, nullptr, nullptr, SINV);

    // softmax -> P bf16
    k_softmax<<<BB*NN, 128>>>((const bf16*)p_Sb, (bf16*)p_P);

    // O = P @ vT -> oT bf16 [b][n][p]
    gemm_kernel<4><<<dim3(2,32,16), 256, DYN_SMEM>>>((const bf16*)p_P, (const bf16*)p_vT,
        nullptr, p_oT,
        NN, PP, MM, (long)NN*MM, (long)MM*PP, (long)NN*PP, nullptr, nullptr, nullptr, 0.f);

    // global-context branch (vgc conv eliminated: gc = wgc@(ix@mask)+bgc)
    k_masklogit<<<dim3(4,16), 256>>>((const float*)p_ixf, wmask, bmask, (float*)p_mask);
    k_masksoftmax<<<16, 256>>>((float*)p_mask);
    k_t<<<dim3(1024,16), 128>>>((const float*)p_ixf, (const float*)p_mask, (float*)p_t);
    k_gc<<<dim3(512,16), 256>>>(wgc, bgc, (const float*)p_t, (float*)p_gc);
    k_gcw<<<dim3(1024,16), 128>>>(wout, beta, (const float*)p_gc, (float*)p_gcw);

    // out[b][c][n] = x + gamma*(oT @ woutT)^T + gcw
    gemm_kernel<2><<<dim3(4,32,16), 256, DYN_SMEM>>>((const bf16*)p_oT, (const bf16*)p_woutT,
        nullptr, d_out,
        NN, CC, PP, (long)NN*PP, 0, (long)CC*NN, x, (const float*)p_gcw, gamma, 0.f);
}

// round 13
// speedup vs baseline: 1.1123x; 1.0011x over previous
#include <cuda_runtime.h>
#include <cuda_bf16.h>
#include <cstdint>
#include <mma.h>
using namespace nvcuda;

#define BB 16
#define CC 1024
#define PP 512
#define NN 4096
#define MM 1024
typedef __nv_bfloat16 bf16;

// ---- scratch (device globals; ALWAYS resolved via cudaGetSymbolAddress) ----
__device__ __align__(16) bf16  g_xb [(long)BB*CC*NN];
__device__ __align__(16) float g_ixf[(long)BB*CC*MM];
__device__ __align__(16) bf16  g_ixb[(long)BB*CC*MM];
__device__ __align__(16) bf16  g_qT [(long)BB*NN*PP];
__device__ __align__(16) bf16  g_k  [(long)BB*PP*MM];
__device__ __align__(16) bf16  g_vT [(long)BB*MM*PP];
__device__ __align__(16) bf16  g_Sb [(long)BB*NN*MM];
__device__ __align__(16) bf16  g_P  [(long)BB*NN*MM];
__device__ __align__(16) bf16  g_oT [(long)BB*NN*PP];
__device__ __align__(16) bf16  g_wqb[PP*CC];
__device__ __align__(16) bf16  g_wkb[PP*CC];
__device__ __align__(16) bf16  g_wvb[PP*CC];
__device__ __align__(16) bf16  g_woutT[PP*CC];
__device__ float g_xsum [BB*CC];
__device__ float g_ixsum[BB*CC];
__device__ float g_qmn[BB*PP];
__device__ float g_kmn[BB*PP];
__device__ float g_mask[BB*MM];
__device__ float g_t[BB*CC];
__device__ float g_gc[BB*PP];
__device__ float g_gcw[BB*CC];

// ---------------- glue kernels ----------------

__global__ void k_f2bf(const float* __restrict__ src, bf16* __restrict__ dst, long n4){
    long i = (long)blockIdx.x*256 + threadIdx.x;
    if (i >= n4) return;
    float4 f = ((const float4*)src)[i];
    ((__nv_bfloat162*)dst)[i*2]   = __floats2bfloat162_rn(f.x, f.y);
    ((__nv_bfloat162*)dst)[i*2+1] = __floats2bfloat162_rn(f.z, f.w);
}

__global__ void k_pool2(const float* __restrict__ x, float* __restrict__ ixf,
                        bf16* __restrict__ ixb, float* __restrict__ xsum,
                        float* __restrict__ ixsum){
    long bc = blockIdx.x;                    // 0..B*C-1
    int tid = threadIdx.x;
    const float* xr = x + bc*(long)NN;
    float s_x = 0.f, s_ix = 0.f;
    #pragma unroll
    for (int i=0;i<4;i++){
        int m = tid + i*256;
        int hk = m >> 5, wk = m & 31;
        const float* base = xr + hk*128 + wk*2;
        float a = base[0], b2 = base[1], c = base[64], d = base[65];
        float v = fmaxf(fmaxf(a, b2), fmaxf(c, d));
        ixf[bc*(long)MM + m] = v;
        ixb[bc*(long)MM + m] = __float2bfloat16(v);
        s_ix += v;
        s_x  += (a + b2) + (c + d);
    }
    __shared__ float r1[256], r2[256];
    r1[tid]=s_x; r2[tid]=s_ix; __syncthreads();
    for (int st=128; st; st>>=1){
        if (tid<st){ r1[tid]+=r1[tid+st]; r2[tid]+=r2[tid+st]; }
        __syncthreads();
    }
    if (tid==0){ xsum[bc] = r1[0]; ixsum[bc] = r2[0]; }
}

__global__ void k_prep(const float* __restrict__ wq, const float* __restrict__ wk,
                       const float* __restrict__ wv, const float* __restrict__ wout,
                       const float* __restrict__ xsum, const float* __restrict__ ixsum,
                       float* __restrict__ qmn, float* __restrict__ kmn,
                       bf16* __restrict__ wqb, bf16* __restrict__ wkb,
                       bf16* __restrict__ wvb, bf16* __restrict__ woutT){
    int p = blockIdx.x, role = blockIdx.y, tid = threadIdx.x;
    if (role < 16){
        int b = role;
        const float* xs = xsum + b*CC;
        const float* is = ixsum + b*CC;
        float sq = 0.f, sk = 0.f;
        for (int c=tid; c<CC; c+=256){
            sq += wq[p*CC+c]*xs[c];
            sk += wk[p*CC+c]*is[c];
        }
        __shared__ float r1[256], r2[256];
        r1[tid]=sq; r2[tid]=sk; __syncthreads();
        for (int st=128; st; st>>=1){
            if (tid<st){ r1[tid]+=r1[tid+st]; r2[tid]+=r2[tid+st]; }
            __syncthreads();
        }
        if (tid==0){ qmn[b*PP+p] = r1[0]*(1.f/NN); kmn[b*PP+p] = r2[0]*(1.f/MM); }
    } else if (role == 16){
        #pragma unroll
        for (int i=0;i<4;i++){
            int c = tid + i*256;
            wqb[p*CC+c] = __float2bfloat16(wq[p*CC+c]);
            wkb[p*CC+c] = __float2bfloat16(wk[p*CC+c]);
            wvb[p*CC+c] = __float2bfloat16(wv[p*CC+c]);
        }
    } else {
        #pragma unroll
        for (int i=0;i<4;i++){
            int c = tid + i*256;
            woutT[p*CC+c] = __float2bfloat16(wout[c*PP+p]);
        }
    }
}

__global__ void k_softmax(const bf16* __restrict__ S, bf16* __restrict__ P){
    long r = blockIdx.x;                     // grid B*N, block 128
    const bf16* src = S + r*MM;
    bf16* dst = P + r*MM;
    int tid = threadIdx.x;
    __shared__ float red[128];
    float v[8];
    #pragma unroll
    for (int i=0;i<8;i++) v[i] = __bfloat162float(src[tid + i*128]);
    float mx = -1e30f;
    #pragma unroll
    for (int i=0;i<8;i++) mx = fmaxf(mx, v[i]);
    red[tid]=mx; __syncthreads();
    for (int st=64;st;st>>=1){ if (tid<st) red[tid]=fmaxf(red[tid],red[tid+st]); __syncthreads(); }
    mx = red[0]; __syncthreads();
    float s = 0.f;
    #pragma unroll
    for (int i=0;i<8;i++){ v[i] = __expf(v[i] - mx); s += v[i]; }
    red[tid]=s; __syncthreads();
    for (int st=64;st;st>>=1){ if (tid<st) red[tid]+=red[tid+st]; __syncthreads(); }
    float rinv = 1.f/red[0];
    #pragma unroll
    for (int i=0;i<8;i++) dst[tid + i*128] = __float2bfloat16(v[i]*rinv);
}

// ---- f32 global-context branch ----
__global__ void k_masklogit(const float* __restrict__ ixf, const float* __restrict__ wmask,
                            const float* __restrict__ bmask, float* __restrict__ mask){
    int m = blockIdx.x*256 + threadIdx.x;    // grid (4,16)
    int b = blockIdx.y;
    const float* ix = ixf + (long)b*CC*MM;
    float s = bmask[0];
    for (int c=0;c<CC;c++) s += wmask[c]*ix[(long)c*MM + m];
    mask[b*MM+m] = s;
}

__global__ void k_masksoftmax(float* __restrict__ mask){  // grid (16), block 256
    int b = blockIdx.x; int tid = threadIdx.x;
    float* row = mask + b*MM;
    __shared__ float red[256];
    float mx = -1e30f;
    for (int m=tid;m<MM;m+=256) mx = fmaxf(mx, row[m]);
    red[tid]=mx; __syncthreads();
    for (int st=128;st;st>>=1){ if (tid<st) red[tid]=fmaxf(red[tid],red[tid+st]); __syncthreads(); }
    mx = red[0]; __syncthreads();
    float s = 0.f;
    for (int m=tid;m<MM;m+=256){ float e = __expf(row[m]-mx); row[m]=e; s+=e; }
    red[tid]=s; __syncthreads();
    for (int st=128;st;st>>=1){ if (tid<st) red[tid]+=red[tid+st]; __syncthreads(); }
    float rinv = 1.f/red[0];
    for (int m=tid;m<MM;m+=256) row[m] *= rinv;
}

__global__ void k_t(const float* __restrict__ ixf, const float* __restrict__ mask,
                    float* __restrict__ t){  // grid (1024,16), block 128
    int c = blockIdx.x, b = blockIdx.y, tid = threadIdx.x;
    const float* ix = ixf + ((long)b*CC + c)*MM;
    float s = 0.f;
    for (int m=tid;m<MM;m+=128) s += ix[m]*mask[b*MM+m];
    __shared__ float red[128];
    red[tid]=s; __syncthreads();
    for (int st=64;st;st>>=1){ if (tid<st) red[tid]+=red[tid+st]; __syncthreads(); }
    if (tid==0) t[b*CC+c] = red[0];
}

__global__ void k_gc(const float* __restrict__ wgc, const float* __restrict__ bgc,
                     const float* __restrict__ t, float* __restrict__ gc){
    int p = blockIdx.x, b = blockIdx.y, tid = threadIdx.x;   // grid (512,16), block 256
    float s = 0.f;
    for (int c=tid;c<CC;c+=256) s += wgc[p*CC+c]*t[b*CC+c];
    __shared__ float red[256];
    red[tid]=s; __syncthreads();
    for (int st=128;st;st>>=1){ if (tid<st) red[tid]+=red[tid+st]; __syncthreads(); }
    if (tid==0) gc[b*PP+p] = red[0] + bgc[p];
}

__global__ void k_gcw(const float* __restrict__ wout, const float* __restrict__ beta,
                      const float* __restrict__ gc, float* __restrict__ gcw){
    int c = blockIdx.x, b = blockIdx.y, tid = threadIdx.x;   // grid (1024,16), block 128
    float s = 0.f;
    for (int p=tid;p<PP;p+=128) s += wout[c*PP+p]*gc[b*PP+p];
    __shared__ float red[128];
    red[tid]=s; __syncthreads();
    for (int st=64;st;st>>=1){ if (tid<st) red[tid]+=red[tid+st]; __syncthreads(); }
    if (tid==0) gcw[b*CC+c] = beta[0]*red[0];
}

// ---- bf16 wmma GEMM, 128x256 tile, 8 warps, 3-stage cp.async, k-chunk 64, 1 sync/chunk ----
// MODE 1: bf16 Out[n*Mdim+m] = acc + bias[m]                      (v conv)
// MODE 2: f32  Out[n*Mdim+m] = xres + gamma[0]*acc + gcw[b*CC+n]  (final)
// MODE 4: bf16 Out[m*Ndim+n] = acc                                (O)
// MODE 5: bf16 Out[n*Mdim+m] = acc - bias[b*PP+m]                 (q whiten)
// MODE 6: bf16 Out[m*Ndim+n] = acc - bias[b*PP+m]                 (k whiten)
// MODE 7: bf16 Out[m*Ndim+n] = acc * hscale                       (S bf16)
#define KC    64
#define LDA_  72      // 64 + 8 pad (bf16); 144B rows
#define LDBW  264     // 256 + 8 pad (bf16); 528B rows
#define LDST  264     // stage ld (f32)
#define A_ST_ELE (128*LDA_)              // bf16 elements per A stage
#define B_ST_ELE (64*LDBW)
#define A_ST_BYTES (A_ST_ELE*2)          // 18432
#define B_ST_BYTES (B_ST_ELE*2)          // 33792
#define DYN_SMEM (3*(A_ST_BYTES+B_ST_BYTES))   // 156672 (> stage 67584)

__device__ __forceinline__ void cp16(void* dst_smem, const void* src_gmem){
    unsigned int d = (unsigned int)__cvta_generic_to_shared(dst_smem);
    asm volatile("cp.async.cg.shared.global [%0], [%1], 16;\n" :: "r"(d), "l"(src_gmem));
}

template<int MODE>
__global__ void __launch_bounds__(256, 1)
gemm_kernel(const bf16* __restrict__ A, const bf16* __restrict__ Bmat,
            const float* __restrict__ bias, void* __restrict__ OutV,
            int Mdim, int Ndim, int Kdim, long sA, long sB, long sOut,
            const float* __restrict__ xres, const float* __restrict__ gcw,
            const float* __restrict__ gamma, float hscale)
{
    extern __shared__ char smraw[];
    bf16* Abuf = (bf16*)smraw;                               // [3][A_ST_ELE]
    bf16* Bbuf = (bf16*)(smraw + 3*A_ST_BYTES);              // [3][B_ST_ELE]
    float* stage = (float*)smraw;                            // epilogue reuse

    const int b = blockIdx.z;
    A    += (long)b * sA;
    Bmat += (long)b * sB;
    const int m0 = blockIdx.y * 128;
    const int n0 = blockIdx.x * 256;
    const int tid = threadIdx.x;
    const int wid = tid >> 5;
    const int warp_m = wid >> 2;      // 0..1
    const int warp_n = wid & 3;       // 0..3

    wmma::fragment<wmma::accumulator,16,16,16,float> acc[4][4];
    #pragma unroll
    for (int i=0;i<4;i++)
        #pragma unroll
        for (int j=0;j<4;j++) wmma::fill_fragment(acc[i][j], 0.f);

    auto load_tiles = [&](int st, int k0){
        #pragma unroll
        for (int p=0;p<4;p++){                               // A: 128x64 = 1024 chunks
            int ch = tid + p*256;
            int r = ch >> 3, c8 = (ch & 7)*8;
            cp16(&Abuf[st*A_ST_ELE + r*LDA_ + c8], &A[(long)(m0+r)*Kdim + k0 + c8]);
        }
        #pragma unroll
        for (int p=0;p<8;p++){                               // B: 64x256 = 2048 chunks
            int ch = tid + p*256;
            int r = ch >> 5, c8 = (ch & 31)*8;
            cp16(&Bbuf[st*B_ST_ELE + r*LDBW + c8], &Bmat[(long)(k0+r)*Ndim + n0 + c8]);
        }
    };

    const int nk = Kdim / KC;
    load_tiles(0, 0);
    asm volatile("cp.async.commit_group;\n");
    load_tiles(1, KC);
    asm volatile("cp.async.commit_group;\n");

    for (int i = 0; i < nk; i++){
        asm volatile("cp.async.wait_group 1;\n");
        __syncthreads();
        if (i + 2 < nk) load_tiles((i+2)%3, (i+2)*KC);
        asm volatile("cp.async.commit_group;\n");

        const bf16* Ab = &Abuf[(i%3)*A_ST_ELE];
        const bf16* Bb = &Bbuf[(i%3)*B_ST_ELE];
        #pragma unroll
        for (int kk=0; kk<KC; kk+=16){
            wmma::fragment<wmma::matrix_a,16,16,16,bf16,wmma::row_major> af[4];
            wmma::fragment<wmma::matrix_b,16,16,16,bf16,wmma::row_major> bfr[4];
            #pragma unroll
            for (int ii=0;ii<4;ii++)
                wmma::load_matrix_sync(af[ii], &Ab[(warp_m*64 + ii*16)*LDA_ + kk], LDA_);
            #pragma unroll
            for (int j=0;j<4;j++)
                wmma::load_matrix_sync(bfr[j], &Bb[kk*LDBW + warp_n*64 + j*16], LDBW);
            #pragma unroll
            for (int ii=0;ii<4;ii++)
                #pragma unroll
                for (int j=0;j<4;j++)
                    wmma::mma_sync(acc[ii][j], af[ii], bfr[j], acc[ii][j]);
        }
    }
    asm volatile("cp.async.wait_group 0;\n");
    __syncthreads();

    const float gmul = (MODE==2) ? gamma[0] : 0.f;
    for (int h=0; h<2; h++){
        if (warp_m == h){
            #pragma unroll
            for (int i=0;i<4;i++)
                #pragma unroll
                for (int j=0;j<4;j++)
                    wmma::store_matrix_sync(&stage[(i*16)*LDST + warp_n*64 + j*16],
                                            acc[i][j], LDST, wmma::mem_row_major);
        }
        __syncthreads();
        if (MODE == 4 || MODE == 6 || MODE == 7){
            bf16* Out = (bf16*)OutV + (long)b*sOut;
            for (int it=0; it<64; it++){
                int idx = it*256 + tid;
                int r = idx >> 8, c = idx & 255;
                int gmi = m0 + h*64 + r, gni = n0 + c;
                float v = stage[r*LDST + c];
                if (MODE == 6) v -= bias[b*PP + gmi];
                if (MODE == 7) v *= hscale;
                Out[(long)gmi*Ndim + gni] = __float2bfloat16(v);
            }
        } else if (MODE == 1 || MODE == 5){
            bf16* Out = (bf16*)OutV + (long)b*sOut;
            for (int it=0; it<64; it++){
                int idx = it*256 + tid;
                int r = idx & 63, c = idx >> 6;
                int gmi = m0 + h*64 + r, gni = n0 + c;
                float bv = (MODE==1) ? bias[gmi] : -bias[b*PP + gmi];
                Out[(long)gni*Mdim + gmi] = __float2bfloat16(stage[r*LDST + c] + bv);
            }
        } else {  // MODE 2
            float* Out = (float*)OutV + (long)b*sOut;
            const float* xr = xres + (long)b*sOut;
            for (int it=0; it<64; it++){
                int idx = it*256 + tid;
                int r = idx & 63, c = idx >> 6;
                int gmi = m0 + h*64 + r;
                int gni = n0 + c;
                long o = (long)gni*Mdim + gmi;
                Out[o] = xr[o] + gmul*stage[r*LDST + c] + gcw[b*CC + gni];
            }
        }
        __syncthreads();
    }
}

extern "C" void kernel_launch(void* const* d_in, const int* in_sizes, int n_in,
                              void* d_out, int out_size) {
    const float* x     = (const float*)d_in[0];
    const float* wq    = (const float*)d_in[1];
    const float* wk    = (const float*)d_in[3];
    const float* wv    = (const float*)d_in[5];
    const float* bv    = (const float*)d_in[6];
    const float* wgc   = (const float*)d_in[7];
    const float* bgc   = (const float*)d_in[8];
    const float* wmask = (const float*)d_in[9];
    const float* bmask = (const float*)d_in[10];
    const float* wout  = (const float*)d_in[11];
    const float* gamma = (const float*)d_in[12];
    const float* beta  = (const float*)d_in[13];

    void *p_xb, *p_ixf, *p_ixb, *p_qT, *p_k, *p_vT, *p_Sb, *p_P, *p_oT;
    void *p_wqb, *p_wkb, *p_wvb, *p_woutT, *p_mask, *p_t, *p_gc, *p_gcw;
    void *p_xsum, *p_ixsum, *p_qmn, *p_kmn;
    cudaGetSymbolAddress(&p_xb,  g_xb);
    cudaGetSymbolAddress(&p_ixf, g_ixf);
    cudaGetSymbolAddress(&p_ixb, g_ixb);
    cudaGetSymbolAddress(&p_qT,  g_qT);
    cudaGetSymbolAddress(&p_k,   g_k);
    cudaGetSymbolAddress(&p_vT,  g_vT);
    cudaGetSymbolAddress(&p_Sb,  g_Sb);
    cudaGetSymbolAddress(&p_P,   g_P);
    cudaGetSymbolAddress(&p_oT,  g_oT);
    cudaGetSymbolAddress(&p_wqb, g_wqb);
    cudaGetSymbolAddress(&p_wkb, g_wkb);
    cudaGetSymbolAddress(&p_wvb, g_wvb);
    cudaGetSymbolAddress(&p_woutT, g_woutT);
    cudaGetSymbolAddress(&p_mask, g_mask);
    cudaGetSymbolAddress(&p_t,   g_t);
    cudaGetSymbolAddress(&p_gc,  g_gc);
    cudaGetSymbolAddress(&p_gcw, g_gcw);
    cudaGetSymbolAddress(&p_xsum, g_xsum);
    cudaGetSymbolAddress(&p_ixsum, g_ixsum);
    cudaGetSymbolAddress(&p_qmn, g_qmn);
    cudaGetSymbolAddress(&p_kmn, g_kmn);

    cudaFuncSetAttribute(gemm_kernel<1>, cudaFuncAttributeMaxDynamicSharedMemorySize, DYN_SMEM);
    cudaFuncSetAttribute(gemm_kernel<2>, cudaFuncAttributeMaxDynamicSharedMemorySize, DYN_SMEM);
    cudaFuncSetAttribute(gemm_kernel<4>, cudaFuncAttributeMaxDynamicSharedMemorySize, DYN_SMEM);
    cudaFuncSetAttribute(gemm_kernel<5>, cudaFuncAttributeMaxDynamicSharedMemorySize, DYN_SMEM);
    cudaFuncSetAttribute(gemm_kernel<6>, cudaFuncAttributeMaxDynamicSharedMemorySize, DYN_SMEM);
    cudaFuncSetAttribute(gemm_kernel<7>, cudaFuncAttributeMaxDynamicSharedMemorySize, DYN_SMEM);

    const float SINV = 0.8838834764831844f;  // 1/(sqrt(512)*0.05)

    // launches: 1..3 prep, then #4..#7 are the big GEMMs
    k_f2bf<<<65536, 256>>>(x, (bf16*)p_xb, (long)BB*CC*NN/4);                       // 1
    k_pool2<<<BB*CC, 256>>>(x, (float*)p_ixf, (bf16*)p_ixb,
                            (float*)p_xsum, (float*)p_ixsum);                       // 2
    k_prep<<<dim3(512,18), 256>>>(wq, wk, wv, wout,
        (const float*)p_xsum, (const float*)p_ixsum,
        (float*)p_qmn, (float*)p_kmn,
        (bf16*)p_wqb, (bf16*)p_wkb, (bf16*)p_wvb, (bf16*)p_woutT);                  // 3

    // q = whiten(wq@x) -> qT [b][n][p]                                             // 4
    gemm_kernel<5><<<dim3(16,4,16), 256, DYN_SMEM>>>((const bf16*)p_wqb, (const bf16*)p_xb,
        (const float*)p_qmn, p_qT,
        PP, NN, CC, 0, (long)CC*NN, (long)NN*PP, nullptr, nullptr, nullptr, 0.f);

    // k = whiten(wk@ix) -> k [b][p][m]                                             // 5
    gemm_kernel<6><<<dim3(4,4,16), 256, DYN_SMEM>>>((const bf16*)p_wkb, (const bf16*)p_ixb,
        (const float*)p_kmn, p_k,
        PP, MM, CC, 0, (long)CC*MM, (long)PP*MM, nullptr, nullptr, nullptr, 0.f);

    // v = wv@ix + bv -> vT [b][m][p]                                               // 6
    gemm_kernel<1><<<dim3(4,4,16), 256, DYN_SMEM>>>((const bf16*)p_wvb, (const bf16*)p_ixb,
        bv, p_vT,
        PP, MM, CC, 0, (long)CC*MM, (long)MM*PP, nullptr, nullptr, nullptr, 0.f);

    // S = (qT @ k) * SINV -> bf16 [b][n][m]                                        // 7
    gemm_kernel<7><<<dim3(4,32,16), 256, DYN_SMEM>>>((const bf16*)p_qT, (const bf16*)p_k,
        nullptr, p_Sb,
        NN, MM, PP, (long)NN*PP, (long)PP*MM, (long)NN*MM, nullptr, nullptr, nullptr, SINV);

    // softmax -> P bf16
    k_softmax<<<BB*NN, 128>>>((const bf16*)p_Sb, (bf16*)p_P);

    // O = P @ vT -> oT bf16 [b][n][p]
    gemm_kernel<4><<<dim3(2,32,16), 256, DYN_SMEM>>>((const bf16*)p_P, (const bf16*)p_vT,
        nullptr, p_oT,
        NN, PP, MM, (long)NN*MM, (long)MM*PP, (long)NN*PP, nullptr, nullptr, nullptr, 0.f);

    // global-context branch (vgc conv eliminated: gc = wgc@(ix@mask)+bgc)
    k_masklogit<<<dim3(4,16), 256>>>((const float*)p_ixf, wmask, bmask, (float*)p_mask);
    k_masksoftmax<<<16, 256>>>((float*)p_mask);
    k_t<<<dim3(1024,16), 128>>>((const float*)p_ixf, (const float*)p_mask, (float*)p_t);
    k_gc<<<dim3(512,16), 256>>>(wgc, bgc, (const float*)p_t, (float*)p_gc);
    k_gcw<<<dim3(1024,16), 128>>>(wout, beta, (const float*)p_gc, (float*)p_gcw);

    // out[b][c][n] = x + gamma*(oT @ woutT)^T + gcw
    gemm_kernel<2><<<dim3(4,32,16), 256, DYN_SMEM>>>((const bf16*)p_oT, (const bf16*)p_woutT,
        nullptr, d_out,
        NN, CC, PP, (long)NN*PP, 0, (long)CC*NN, x, (const float*)p_gcw, gamma, 0.f);
}

// round 14
// speedup vs baseline: 1.1123x; 1.0000x over previous
#include <cuda_runtime.h>
#include <cuda_bf16.h>
#include <cstdint>
#include <mma.h>
using namespace nvcuda;

#define BB 16
#define CC 1024
#define PP 512
#define NN 4096
#define MM 1024
typedef __nv_bfloat16 bf16;

// ---- scratch (device globals; ALWAYS resolved via cudaGetSymbolAddress) ----
__device__ __align__(16) bf16  g_xb [(long)BB*CC*NN];
__device__ __align__(16) float g_ixf[(long)BB*CC*MM];
__device__ __align__(16) bf16  g_ixb[(long)BB*CC*MM];
__device__ __align__(16) bf16  g_qT [(long)BB*NN*PP];
__device__ __align__(16) bf16  g_k  [(long)BB*PP*MM];
__device__ __align__(16) bf16  g_vT [(long)BB*MM*PP];
__device__ __align__(16) bf16  g_Sb [(long)BB*NN*MM];
__device__ __align__(16) bf16  g_P  [(long)BB*NN*MM];
__device__ __align__(16) bf16  g_oT [(long)BB*NN*PP];
__device__ __align__(16) bf16  g_wqb[PP*CC];
__device__ __align__(16) bf16  g_wkb[PP*CC];
__device__ __align__(16) bf16  g_wvb[PP*CC];
__device__ __align__(16) bf16  g_woutT[PP*CC];
__device__ float g_xsum [BB*CC];
__device__ float g_ixsum[BB*CC];
__device__ float g_qmn[BB*PP];
__device__ float g_kmn[BB*PP];
__device__ float g_mask[BB*MM];
__device__ float g_t[BB*CC];
__device__ float g_gc[BB*PP];
__device__ float g_gcw[BB*CC];

// ---------------- glue kernels ----------------

__global__ void k_f2bf(const float* __restrict__ src, bf16* __restrict__ dst, long n4){
    long i = (long)blockIdx.x*256 + threadIdx.x;
    if (i >= n4) return;
    float4 f = ((const float4*)src)[i];
    ((__nv_bfloat162*)dst)[i*2]   = __floats2bfloat162_rn(f.x, f.y);
    ((__nv_bfloat162*)dst)[i*2+1] = __floats2bfloat162_rn(f.z, f.w);
}

__global__ void k_pool2(const float* __restrict__ x, float* __restrict__ ixf,
                        bf16* __restrict__ ixb, float* __restrict__ xsum,
                        float* __restrict__ ixsum){
    long bc = blockIdx.x;                    // 0..B*C-1
    int tid = threadIdx.x;
    const float* xr = x + bc*(long)NN;
    float s_x = 0.f, s_ix = 0.f;
    #pragma unroll
    for (int i=0;i<4;i++){
        int m = tid + i*256;
        int hk = m >> 5, wk = m & 31;
        const float* base = xr + hk*128 + wk*2;
        float a = base[0], b2 = base[1], c = base[64], d = base[65];
        float v = fmaxf(fmaxf(a, b2), fmaxf(c, d));
        ixf[bc*(long)MM + m] = v;
        ixb[bc*(long)MM + m] = __float2bfloat16(v);
        s_ix += v;
        s_x  += (a + b2) + (c + d);
    }
    __shared__ float r1[256], r2[256];
    r1[tid]=s_x; r2[tid]=s_ix; __syncthreads();
    for (int st=128; st; st>>=1){
        if (tid<st){ r1[tid]+=r1[tid+st]; r2[tid]+=r2[tid+st]; }
        __syncthreads();
    }
    if (tid==0){ xsum[bc] = r1[0]; ixsum[bc] = r2[0]; }
}

__global__ void k_prep(const float* __restrict__ wq, const float* __restrict__ wk,
                       const float* __restrict__ wv, const float* __restrict__ wout,
                       const float* __restrict__ xsum, const float* __restrict__ ixsum,
                       float* __restrict__ qmn, float* __restrict__ kmn,
                       bf16* __restrict__ wqb, bf16* __restrict__ wkb,
                       bf16* __restrict__ wvb, bf16* __restrict__ woutT){
    int p = blockIdx.x, role = blockIdx.y, tid = threadIdx.x;
    if (role < 16){
        int b = role;
        const float* xs = xsum + b*CC;
        const float* is = ixsum + b*CC;
        float sq = 0.f, sk = 0.f;
        for (int c=tid; c<CC; c+=256){
            sq += wq[p*CC+c]*xs[c];
            sk += wk[p*CC+c]*is[c];
        }
        __shared__ float r1[256], r2[256];
        r1[tid]=sq; r2[tid]=sk; __syncthreads();
        for (int st=128; st; st>>=1){
            if (tid<st){ r1[tid]+=r1[tid+st]; r2[tid]+=r2[tid+st]; }
            __syncthreads();
        }
        if (tid==0){ qmn[b*PP+p] = r1[0]*(1.f/NN); kmn[b*PP+p] = r2[0]*(1.f/MM); }
    } else if (role == 16){
        #pragma unroll
        for (int i=0;i<4;i++){
            int c = tid + i*256;
            wqb[p*CC+c] = __float2bfloat16(wq[p*CC+c]);
            wkb[p*CC+c] = __float2bfloat16(wk[p*CC+c]);
            wvb[p*CC+c] = __float2bfloat16(wv[p*CC+c]);
        }
    } else {
        #pragma unroll
        for (int i=0;i<4;i++){
            int c = tid + i*256;
            woutT[p*CC+c] = __float2bfloat16(wout[c*PP+p]);
        }
    }
}

__global__ void k_softmax(const bf16* __restrict__ S, bf16* __restrict__ P){
    long r = blockIdx.x;                     // grid B*N, block 128
    const bf16* src = S + r*MM;
    bf16* dst = P + r*MM;
    int tid = threadIdx.x;
    __shared__ float red[128];
    float v[8];
    #pragma unroll
    for (int i=0;i<8;i++) v[i] = __bfloat162float(src[tid + i*128]);
    float mx = -1e30f;
    #pragma unroll
    for (int i=0;i<8;i++) mx = fmaxf(mx, v[i]);
    red[tid]=mx; __syncthreads();
    for (int st=64;st;st>>=1){ if (tid<st) red[tid]=fmaxf(red[tid],red[tid+st]); __syncthreads(); }
    mx = red[0]; __syncthreads();
    float s = 0.f;
    #pragma unroll
    for (int i=0;i<8;i++){ v[i] = __expf(v[i] - mx); s += v[i]; }
    red[tid]=s; __syncthreads();
    for (int st=64;st;st>>=1){ if (tid<st) red[tid]+=red[tid+st]; __syncthreads(); }
    float rinv = 1.f/red[0];
    #pragma unroll
    for (int i=0;i<8;i++) dst[tid + i*128] = __float2bfloat16(v[i]*rinv);
}

// ---- f32 global-context branch ----
__global__ void k_masklogit(const float* __restrict__ ixf, const float* __restrict__ wmask,
                            const float* __restrict__ bmask, float* __restrict__ mask){
    int m = blockIdx.x*256 + threadIdx.x;    // grid (4,16)
    int b = blockIdx.y;
    const float* ix = ixf + (long)b*CC*MM;
    float s = bmask[0];
    for (int c=0;c<CC;c++) s += wmask[c]*ix[(long)c*MM + m];
    mask[b*MM+m] = s;
}

__global__ void k_masksoftmax(float* __restrict__ mask){  // grid (16), block 256
    int b = blockIdx.x; int tid = threadIdx.x;
    float* row = mask + b*MM;
    __shared__ float red[256];
    float mx = -1e30f;
    for (int m=tid;m<MM;m+=256) mx = fmaxf(mx, row[m]);
    red[tid]=mx; __syncthreads();
    for (int st=128;st;st>>=1){ if (tid<st) red[tid]=fmaxf(red[tid],red[tid+st]); __syncthreads(); }
    mx = red[0]; __syncthreads();
    float s = 0.f;
    for (int m=tid;m<MM;m+=256){ float e = __expf(row[m]-mx); row[m]=e; s+=e; }
    red[tid]=s; __syncthreads();
    for (int st=128;st;st>>=1){ if (tid<st) red[tid]+=red[tid+st]; __syncthreads(); }
    float rinv = 1.f/red[0];
    for (int m=tid;m<MM;m+=256) row[m] *= rinv;
}

__global__ void k_t(const float* __restrict__ ixf, const float* __restrict__ mask,
                    float* __restrict__ t){  // grid (1024,16), block 128
    int c = blockIdx.x, b = blockIdx.y, tid = threadIdx.x;
    const float* ix = ixf + ((long)b*CC + c)*MM;
    float s = 0.f;
    for (int m=tid;m<MM;m+=128) s += ix[m]*mask[b*MM+m];
    __shared__ float red[128];
    red[tid]=s; __syncthreads();
    for (int st=64;st;st>>=1){ if (tid<st) red[tid]+=red[tid+st]; __syncthreads(); }
    if (tid==0) t[b*CC+c] = red[0];
}

__global__ void k_gc(const float* __restrict__ wgc, const float* __restrict__ bgc,
                     const float* __restrict__ t, float* __restrict__ gc){
    int p = blockIdx.x, b = blockIdx.y, tid = threadIdx.x;   // grid (512,16), block 256
    float s = 0.f;
    for (int c=tid;c<CC;c+=256) s += wgc[p*CC+c]*t[b*CC+c];
    __shared__ float red[256];
    red[tid]=s; __syncthreads();
    for (int st=128;st;st>>=1){ if (tid<st) red[tid]+=red[tid+st]; __syncthreads(); }
    if (tid==0) gc[b*PP+p] = red[0] + bgc[p];
}

__global__ void k_gcw(const float* __restrict__ wout, const float* __restrict__ beta,
                      const float* __restrict__ gc, float* __restrict__ gcw){
    int c = blockIdx.x, b = blockIdx.y, tid = threadIdx.x;   // grid (1024,16), block 128
    float s = 0.f;
    for (int p=tid;p<PP;p+=128) s += wout[c*PP+p]*gc[b*PP+p];
    __shared__ float red[128];
    red[tid]=s; __syncthreads();
    for (int st=64;st;st>>=1){ if (tid<st) red[tid]+=red[tid+st]; __syncthreads(); }
    if (tid==0) gcw[b*CC+c] = beta[0]*red[0];
}

// ---- bf16 wmma GEMM, 128x256 tile, 8 warps, 3-stage cp.async, k-chunk 64, 1 sync/chunk ----
// MODE 1: bf16 Out[n*Mdim+m] = acc + bias[m]                      (v conv)
// MODE 2: f32  Out[n*Mdim+m] = xres + gamma[0]*acc + gcw[b*CC+n]  (final)
// MODE 4: bf16 Out[m*Ndim+n] = acc                                (O)
// MODE 5: bf16 Out[n*Mdim+m] = acc - bias[b*PP+m]                 (q whiten)
// MODE 6: bf16 Out[m*Ndim+n] = acc - bias[b*PP+m]                 (k whiten)
// MODE 7: bf16 Out[m*Ndim+n] = acc * hscale                       (S bf16)
#define KC    64
#define LDA_  72      // 64 + 8 pad (bf16); 144B rows
#define LDBW  264     // 256 + 8 pad (bf16); 528B rows
#define LDST  264     // stage ld (f32)
#define A_ST_ELE (128*LDA_)              // bf16 elements per A stage
#define B_ST_ELE (64*LDBW)
#define A_ST_BYTES (A_ST_ELE*2)          // 18432
#define B_ST_BYTES (B_ST_ELE*2)          // 33792
#define DYN_SMEM (3*(A_ST_BYTES+B_ST_BYTES))   // 156672 (> stage 67584)

__device__ __forceinline__ void cp16(void* dst_smem, const void* src_gmem){
    unsigned int d = (unsigned int)__cvta_generic_to_shared(dst_smem);
    asm volatile("cp.async.cg.shared.global [%0], [%1], 16;\n" :: "r"(d), "l"(src_gmem));
}

template<int MODE>
__global__ void __launch_bounds__(256, 1)
gemm_kernel(const bf16* __restrict__ A, const bf16* __restrict__ Bmat,
            const float* __restrict__ bias, void* __restrict__ OutV,
            int Mdim, int Ndim, int Kdim, long sA, long sB, long sOut,
            const float* __restrict__ xres, const float* __restrict__ gcw,
            const float* __restrict__ gamma, float hscale)
{
    extern __shared__ char smraw[];
    bf16* Abuf = (bf16*)smraw;                               // [3][A_ST_ELE]
    bf16* Bbuf = (bf16*)(smraw + 3*A_ST_BYTES);              // [3][B_ST_ELE]
    float* stage = (float*)smraw;                            // epilogue reuse

    const int b = blockIdx.z;
    A    += (long)b * sA;
    Bmat += (long)b * sB;
    const int m0 = blockIdx.y * 128;
    const int n0 = blockIdx.x * 256;
    const int tid = threadIdx.x;
    const int wid = tid >> 5;
    const int warp_m = wid >> 2;      // 0..1
    const int warp_n = wid & 3;       // 0..3

    wmma::fragment<wmma::accumulator,16,16,16,float> acc[4][4];
    #pragma unroll
    for (int i=0;i<4;i++)
        #pragma unroll
        for (int j=0;j<4;j++) wmma::fill_fragment(acc[i][j], 0.f);

    auto load_tiles = [&](int st, int k0){
        #pragma unroll
        for (int p=0;p<4;p++){                               // A: 128x64 = 1024 chunks
            int ch = tid + p*256;
            int r = ch >> 3, c8 = (ch & 7)*8;
            cp16(&Abuf[st*A_ST_ELE + r*LDA_ + c8], &A[(long)(m0+r)*Kdim + k0 + c8]);
        }
        #pragma unroll
        for (int p=0;p<8;p++){                               // B: 64x256 = 2048 chunks
            int ch = tid + p*256;
            int r = ch >> 5, c8 = (ch & 31)*8;
            cp16(&Bbuf[st*B_ST_ELE + r*LDBW + c8], &Bmat[(long)(k0+r)*Ndim + n0 + c8]);
        }
    };

    const int nk = Kdim / KC;
    load_tiles(0, 0);
    asm volatile("cp.async.commit_group;\n");
    load_tiles(1, KC);
    asm volatile("cp.async.commit_group;\n");

    for (int i = 0; i < nk; i++){
        asm volatile("cp.async.wait_group 1;\n");
        __syncthreads();
        if (i + 2 < nk) load_tiles((i+2)%3, (i+2)*KC);
        asm volatile("cp.async.commit_group;\n");

        const bf16* Ab = &Abuf[(i%3)*A_ST_ELE];
        const bf16* Bb = &Bbuf[(i%3)*B_ST_ELE];
        #pragma unroll
        for (int kk=0; kk<KC; kk+=16){
            wmma::fragment<wmma::matrix_a,16,16,16,bf16,wmma::row_major> af[4];
            wmma::fragment<wmma::matrix_b,16,16,16,bf16,wmma::row_major> bfr[4];
            #pragma unroll
            for (int ii=0;ii<4;ii++)
                wmma::load_matrix_sync(af[ii], &Ab[(warp_m*64 + ii*16)*LDA_ + kk], LDA_);
            #pragma unroll
            for (int j=0;j<4;j++)
                wmma::load_matrix_sync(bfr[j], &Bb[kk*LDBW + warp_n*64 + j*16], LDBW);
            #pragma unroll
            for (int ii=0;ii<4;ii++)
                #pragma unroll
                for (int j=0;j<4;j++)
                    wmma::mma_sync(acc[ii][j], af[ii], bfr[j], acc[ii][j]);
        }
    }
    asm volatile("cp.async.wait_group 0;\n");
    __syncthreads();

    const float gmul = (MODE==2) ? gamma[0] : 0.f;
    for (int h=0; h<2; h++){
        if (warp_m == h){
            #pragma unroll
            for (int i=0;i<4;i++)
                #pragma unroll
                for (int j=0;j<4;j++)
                    wmma::store_matrix_sync(&stage[(i*16)*LDST + warp_n*64 + j*16],
                                            acc[i][j], LDST, wmma::mem_row_major);
        }
        __syncthreads();
        if (MODE == 4 || MODE == 6 || MODE == 7){
            bf16* Out = (bf16*)OutV + (long)b*sOut;
            for (int it=0; it<64; it++){
                int idx = it*256 + tid;
                int r = idx >> 8, c = idx & 255;
                int gmi = m0 + h*64 + r, gni = n0 + c;
                float v = stage[r*LDST + c];
                if (MODE == 6) v -= bias[b*PP + gmi];
                if (MODE == 7) v *= hscale;
                Out[(long)gmi*Ndim + gni] = __float2bfloat16(v);
            }
        } else if (MODE == 1 || MODE == 5){
            bf16* Out = (bf16*)OutV + (long)b*sOut;
            for (int it=0; it<64; it++){
                int idx = it*256 + tid;
                int r = idx & 63, c = idx >> 6;
                int gmi = m0 + h*64 + r, gni = n0 + c;
                float bv = (MODE==1) ? bias[gmi] : -bias[b*PP + gmi];
                Out[(long)gni*Mdim + gmi] = __float2bfloat16(stage[r*LDST + c] + bv);
            }
        } else {  // MODE 2
            float* Out = (float*)OutV + (long)b*sOut;
            const float* xr = xres + (long)b*sOut;
            for (int it=0; it<64; it++){
                int idx = it*256 + tid;
                int r = idx & 63, c = idx >> 6;
                int gmi = m0 + h*64 + r;
                int gni = n0 + c;
                long o = (long)gni*Mdim + gmi;
                Out[o] = xr[o] + gmul*stage[r*LDST + c] + gcw[b*CC + gni];
            }
        }
        __syncthreads();
    }
}

extern "C" void kernel_launch(void* const* d_in, const int* in_sizes, int n_in,
                              void* d_out, int out_size) {
    const float* x     = (const float*)d_in[0];
    const float* wq    = (const float*)d_in[1];
    const float* wk    = (const float*)d_in[3];
    const float* wv    = (const float*)d_in[5];
    const float* bv    = (const float*)d_in[6];
    const float* wgc   = (const float*)d_in[7];
    const float* bgc   = (const float*)d_in[8];
    const float* wmask = (const float*)d_in[9];
    const float* bmask = (const float*)d_in[10];
    const float* wout  = (const float*)d_in[11];
    const float* gamma = (const float*)d_in[12];
    const float* beta  = (const float*)d_in[13];

    void *p_xb, *p_ixf, *p_ixb, *p_qT, *p_k, *p_vT, *p_Sb, *p_P, *p_oT;
    void *p_wqb, *p_wkb, *p_wvb, *p_woutT, *p_mask, *p_t, *p_gc, *p_gcw;
    void *p_xsum, *p_ixsum, *p_qmn, *p_kmn;
    cudaGetSymbolAddress(&p_xb,  g_xb);
    cudaGetSymbolAddress(&p_ixf, g_ixf);
    cudaGetSymbolAddress(&p_ixb, g_ixb);
    cudaGetSymbolAddress(&p_qT,  g_qT);
    cudaGetSymbolAddress(&p_k,   g_k);
    cudaGetSymbolAddress(&p_vT,  g_vT);
    cudaGetSymbolAddress(&p_Sb,  g_Sb);
    cudaGetSymbolAddress(&p_P,   g_P);
    cudaGetSymbolAddress(&p_oT,  g_oT);
    cudaGetSymbolAddress(&p_wqb, g_wqb);
    cudaGetSymbolAddress(&p_wkb, g_wkb);
    cudaGetSymbolAddress(&p_wvb, g_wvb);
    cudaGetSymbolAddress(&p_woutT, g_woutT);
    cudaGetSymbolAddress(&p_mask, g_mask);
    cudaGetSymbolAddress(&p_t,   g_t);
    cudaGetSymbolAddress(&p_gc,  g_gc);
    cudaGetSymbolAddress(&p_gcw, g_gcw);
    cudaGetSymbolAddress(&p_xsum, g_xsum);
    cudaGetSymbolAddress(&p_ixsum, g_ixsum);
    cudaGetSymbolAddress(&p_qmn, g_qmn);
    cudaGetSymbolAddress(&p_kmn, g_kmn);

    cudaFuncSetAttribute(gemm_kernel<1>, cudaFuncAttributeMaxDynamicSharedMemorySize, DYN_SMEM);
    cudaFuncSetAttribute(gemm_kernel<2>, cudaFuncAttributeMaxDynamicSharedMemorySize, DYN_SMEM);
    cudaFuncSetAttribute(gemm_kernel<4>, cudaFuncAttributeMaxDynamicSharedMemorySize, DYN_SMEM);
    cudaFuncSetAttribute(gemm_kernel<5>, cudaFuncAttributeMaxDynamicSharedMemorySize, DYN_SMEM);
    cudaFuncSetAttribute(gemm_kernel<6>, cudaFuncAttributeMaxDynamicSharedMemorySize, DYN_SMEM);
    cudaFuncSetAttribute(gemm_kernel<7>, cudaFuncAttributeMaxDynamicSharedMemorySize, DYN_SMEM);

    const float SINV = 0.8838834764831844f;  // 1/(sqrt(512)*0.05)

    // launches: 1..3 prep, then #4..#7 are the big GEMMs
    k_f2bf<<<65536, 256>>>(x, (bf16*)p_xb, (long)BB*CC*NN/4);                       // 1
    k_pool2<<<BB*CC, 256>>>(x, (float*)p_ixf, (bf16*)p_ixb,
                            (float*)p_xsum, (float*)p_ixsum);                       // 2
    k_prep<<<dim3(512,18), 256>>>(wq, wk, wv, wout,
        (const float*)p_xsum, (const float*)p_ixsum,
        (float*)p_qmn, (float*)p_kmn,
        (bf16*)p_wqb, (bf16*)p_wkb, (bf16*)p_wvb, (bf16*)p_woutT);                  // 3

    // q = whiten(wq@x) -> qT [b][n][p]                                             // 4
    gemm_kernel<5><<<dim3(16,4,16), 256, DYN_SMEM>>>((const bf16*)p_wqb, (const bf16*)p_xb,
        (const float*)p_qmn, p_qT,
        PP, NN, CC, 0, (long)CC*NN, (long)NN*PP, nullptr, nullptr, nullptr, 0.f);

    // k = whiten(wk@ix) -> k [b][p][m]                                             // 5
    gemm_kernel<6><<<dim3(4,4,16), 256, DYN_SMEM>>>((const bf16*)p_wkb, (const bf16*)p_ixb,
        (const float*)p_kmn, p_k,
        PP, MM, CC, 0, (long)CC*MM, (long)PP*MM, nullptr, nullptr, nullptr, 0.f);

    // v = wv@ix + bv -> vT [b][m][p]                                               // 6
    gemm_kernel<1><<<dim3(4,4,16), 256, DYN_SMEM>>>((const bf16*)p_wvb, (const bf16*)p_ixb,
        bv, p_vT,
        PP, MM, CC, 0, (long)CC*MM, (long)MM*PP, nullptr, nullptr, nullptr, 0.f);

    // S = (qT @ k) * SINV -> bf16 [b][n][m]                                        // 7
    gemm_kernel<7><<<dim3(4,32,16), 256, DYN_SMEM>>>((const bf16*)p_qT, (const bf16*)p_k,
        nullptr, p_Sb,
        NN, MM, PP, (long)NN*PP, (long)PP*MM, (long)NN*MM, nullptr, nullptr, nullptr, SINV);

    // softmax -> P bf16
    k_softmax<<<BB*NN, 128>>>((const bf16*)p_Sb, (bf16*)p_P);

    // O = P @ vT -> oT bf16 [b][n][p]
    gemm_kernel<4><<<dim3(2,32,16), 256, DYN_SMEM>>>((const bf16*)p_P, (const bf16*)p_vT,
        nullptr, p_oT,
        NN, PP, MM, (long)NN*MM, (long)MM*PP, (long)NN*PP, nullptr, nullptr, nullptr, 0.f);

    // global-context branch (vgc conv eliminated: gc = wgc@(ix@mask)+bgc)
    k_masklogit<<<dim3(4,16), 256>>>((const float*)p_ixf, wmask, bmask, (float*)p_mask);
    k_masksoftmax<<<16, 256>>>((float*)p_mask);
    k_t<<<dim3(1024,16), 128>>>((const float*)p_ixf, (const float*)p_mask, (float*)p_t);
    k_gc<<<dim3(512,16), 256>>>(wgc, bgc, (const float*)p_t, (float*)p_gc);
    k_gcw<<<dim3(1024,16), 128>>>(wout, beta, (const float*)p_gc, (float*)p_gcw);

    // out[b][c][n] = x + gamma*(oT @ woutT)^T + gcw
    gemm_kernel<2><<<dim3(4,32,16), 256, DYN_SMEM>>>((const bf16*)p_oT, (const bf16*)p_woutT,
        nullptr, d_out,
        NN, CC, PP, (long)NN*PP, 0, (long)CC*NN, x, (const float*)p_gcw, gamma, 0.f);
}

// round 15
// speedup vs baseline: 1.1134x; 1.0009x over previous
#include <cuda_runtime.h>
#include <cuda_bf16.h>
#include <cstdint>
#include <mma.h>
using namespace nvcuda;

#define BB 16
#define CC 1024
#define PP 512
#define NN 4096
#define MM 1024
typedef __nv_bfloat16 bf16;

// ---- scratch (device globals; ALWAYS resolved via cudaGetSymbolAddress) ----
__device__ __align__(16) bf16  g_xb [(long)BB*CC*NN];
__device__ __align__(16) float g_ixf[(long)BB*CC*MM];
__device__ __align__(16) bf16  g_ixb[(long)BB*CC*MM];
__device__ __align__(16) bf16  g_qT [(long)BB*NN*PP];
__device__ __align__(16) bf16  g_k  [(long)BB*PP*MM];
__device__ __align__(16) bf16  g_vT [(long)BB*MM*PP];
__device__ __align__(16) bf16  g_Sb [(long)BB*NN*MM];
__device__ __align__(16) bf16  g_P  [(long)BB*NN*MM];
__device__ __align__(16) bf16  g_oT [(long)BB*NN*PP];
__device__ __align__(16) bf16  g_wqb[PP*CC];
__device__ __align__(16) bf16  g_wkb[PP*CC];
__device__ __align__(16) bf16  g_wvb[PP*CC];
__device__ __align__(16) bf16  g_woutT[PP*CC];
__device__ float g_xsum [BB*CC];
__device__ float g_ixsum[BB*CC];
__device__ float g_qmn[BB*PP];
__device__ float g_kmn[BB*PP];
__device__ float g_mask[BB*MM];
__device__ float g_t[BB*CC];
__device__ float g_gc[BB*PP];
__device__ float g_gcw[BB*CC];

// ---------------- glue kernels ----------------

__global__ void k_f2bf(const float* __restrict__ src, bf16* __restrict__ dst, long n4){
    long i = (long)blockIdx.x*256 + threadIdx.x;
    if (i >= n4) return;
    float4 f = ((const float4*)src)[i];
    ((__nv_bfloat162*)dst)[i*2]   = __floats2bfloat162_rn(f.x, f.y);
    ((__nv_bfloat162*)dst)[i*2+1] = __floats2bfloat162_rn(f.z, f.w);
}

__global__ void k_pool2(const float* __restrict__ x, float* __restrict__ ixf,
                        bf16* __restrict__ ixb, float* __restrict__ xsum,
                        float* __restrict__ ixsum){
    long bc = blockIdx.x;                    // 0..B*C-1
    int tid = threadIdx.x;
    const float* xr = x + bc*(long)NN;
    float s_x = 0.f, s_ix = 0.f;
    #pragma unroll
    for (int i=0;i<4;i++){
        int m = tid + i*256;
        int hk = m >> 5, wk = m & 31;
        const float* base = xr + hk*128 + wk*2;
        float a = base[0], b2 = base[1], c = base[64], d = base[65];
        float v = fmaxf(fmaxf(a, b2), fmaxf(c, d));
        ixf[bc*(long)MM + m] = v;
        ixb[bc*(long)MM + m] = __float2bfloat16(v);
        s_ix += v;
        s_x  += (a + b2) + (c + d);
    }
    __shared__ float r1[256], r2[256];
    r1[tid]=s_x; r2[tid]=s_ix; __syncthreads();
    for (int st=128; st; st>>=1){
        if (tid<st){ r1[tid]+=r1[tid+st]; r2[tid]+=r2[tid+st]; }
        __syncthreads();
    }
    if (tid==0){ xsum[bc] = r1[0]; ixsum[bc] = r2[0]; }
}

__global__ void k_prep(const float* __restrict__ wq, const float* __restrict__ wk,
                       const float* __restrict__ wv, const float* __restrict__ wout,
                       const float* __restrict__ xsum, const float* __restrict__ ixsum,
                       float* __restrict__ qmn, float* __restrict__ kmn,
                       bf16* __restrict__ wqb, bf16* __restrict__ wkb,
                       bf16* __restrict__ wvb, bf16* __restrict__ woutT){
    int p = blockIdx.x, role = blockIdx.y, tid = threadIdx.x;
    if (role < 16){
        int b = role;
        const float* xs = xsum + b*CC;
        const float* is = ixsum + b*CC;
        float sq = 0.f, sk = 0.f;
        for (int c=tid; c<CC; c+=256){
            sq += wq[p*CC+c]*xs[c];
            sk += wk[p*CC+c]*is[c];
        }
        __shared__ float r1[256], r2[256];
        r1[tid]=sq; r2[tid]=sk; __syncthreads();
        for (int st=128; st; st>>=1){
            if (tid<st){ r1[tid]+=r1[tid+st]; r2[tid]+=r2[tid+st]; }
            __syncthreads();
        }
        if (tid==0){ qmn[b*PP+p] = r1[0]*(1.f/NN); kmn[b*PP+p] = r2[0]*(1.f/MM); }
    } else if (role == 16){
        #pragma unroll
        for (int i=0;i<4;i++){
            int c = tid + i*256;
            wqb[p*CC+c] = __float2bfloat16(wq[p*CC+c]);
            wkb[p*CC+c] = __float2bfloat16(wk[p*CC+c]);
            wvb[p*CC+c] = __float2bfloat16(wv[p*CC+c]);
        }
    } else {
        #pragma unroll
        for (int i=0;i<4;i++){
            int c = tid + i*256;
            woutT[p*CC+c] = __float2bfloat16(wout[c*PP+p]);
        }
    }
}

__global__ void k_softmax(const bf16* __restrict__ S, bf16* __restrict__ P){
    long r = blockIdx.x;                     // grid B*N, block 128
    const bf16* src = S + r*MM;
    bf16* dst = P + r*MM;
    int tid = threadIdx.x;
    __shared__ float red[128];
    float v[8];
    #pragma unroll
    for (int i=0;i<8;i++) v[i] = __bfloat162float(src[tid + i*128]);
    float mx = -1e30f;
    #pragma unroll
    for (int i=0;i<8;i++) mx = fmaxf(mx, v[i]);
    red[tid]=mx; __syncthreads();
    for (int st=64;st;st>>=1){ if (tid<st) red[tid]=fmaxf(red[tid],red[tid+st]); __syncthreads(); }
    mx = red[0]; __syncthreads();
    float s = 0.f;
    #pragma unroll
    for (int i=0;i<8;i++){ v[i] = __expf(v[i] - mx); s += v[i]; }
    red[tid]=s; __syncthreads();
    for (int st=64;st;st>>=1){ if (tid<st) red[tid]+=red[tid+st]; __syncthreads(); }
    float rinv = 1.f/red[0];
    #pragma unroll
    for (int i=0;i<8;i++) dst[tid + i*128] = __float2bfloat16(v[i]*rinv);
}

// ---- f32 global-context branch ----
__global__ void k_masklogit(const float* __restrict__ ixf, const float* __restrict__ wmask,
                            const float* __restrict__ bmask, float* __restrict__ mask){
    int m = blockIdx.x*256 + threadIdx.x;    // grid (4,16)
    int b = blockIdx.y;
    const float* ix = ixf + (long)b*CC*MM;
    float s = bmask[0];
    for (int c=0;c<CC;c++) s += wmask[c]*ix[(long)c*MM + m];
    mask[b*MM+m] = s;
}

__global__ void k_masksoftmax(float* __restrict__ mask){  // grid (16), block 256
    int b = blockIdx.x; int tid = threadIdx.x;
    float* row = mask + b*MM;
    __shared__ float red[256];
    float mx = -1e30f;
    for (int m=tid;m<MM;m+=256) mx = fmaxf(mx, row[m]);
    red[tid]=mx; __syncthreads();
    for (int st=128;st;st>>=1){ if (tid<st) red[tid]=fmaxf(red[tid],red[tid+st]); __syncthreads(); }
    mx = red[0]; __syncthreads();
    float s = 0.f;
    for (int m=tid;m<MM;m+=256){ float e = __expf(row[m]-mx); row[m]=e; s+=e; }
    red[tid]=s; __syncthreads();
    for (int st=128;st;st>>=1){ if (tid<st) red[tid]+=red[tid+st]; __syncthreads(); }
    float rinv = 1.f/red[0];
    for (int m=tid;m<MM;m+=256) row[m] *= rinv;
}

__global__ void k_t(const float* __restrict__ ixf, const float* __restrict__ mask,
                    float* __restrict__ t){  // grid (1024,16), block 128
    int c = blockIdx.x, b = blockIdx.y, tid = threadIdx.x;
    const float* ix = ixf + ((long)b*CC + c)*MM;
    float s = 0.f;
    for (int m=tid;m<MM;m+=128) s += ix[m]*mask[b*MM+m];
    __shared__ float red[128];
    red[tid]=s; __syncthreads();
    for (int st=64;st;st>>=1){ if (tid<st) red[tid]+=red[tid+st]; __syncthreads(); }
    if (tid==0) t[b*CC+c] = red[0];
}

__global__ void k_gc(const float* __restrict__ wgc, const float* __restrict__ bgc,
                     const float* __restrict__ t, float* __restrict__ gc){
    int p = blockIdx.x, b = blockIdx.y, tid = threadIdx.x;   // grid (512,16), block 256
    float s = 0.f;
    for (int c=tid;c<CC;c+=256) s += wgc[p*CC+c]*t[b*CC+c];
    __shared__ float red[256];
    red[tid]=s; __syncthreads();
    for (int st=128;st;st>>=1){ if (tid<st) red[tid]+=red[tid+st]; __syncthreads(); }
    if (tid==0) gc[b*PP+p] = red[0] + bgc[p];
}

__global__ void k_gcw(const float* __restrict__ wout, const float* __restrict__ beta,
                      const float* __restrict__ gc, float* __restrict__ gcw){
    int c = blockIdx.x, b = blockIdx.y, tid = threadIdx.x;   // grid (1024,16), block 128
    float s = 0.f;
    for (int p=tid;p<PP;p+=128) s += wout[c*PP+p]*gc[b*PP+p];
    __shared__ float red[128];
    red[tid]=s; __syncthreads();
    for (int st=64;st;st>>=1){ if (tid<st) red[tid]+=red[tid+st]; __syncthreads(); }
    if (tid==0) gcw[b*CC+c] = beta[0]*red[0];
}

// ---- bf16 wmma GEMM, 128x256 tile, 8 warps, 3-stage cp.async, k-chunk 64, 1 sync/chunk ----
// MODE 1: bf16 Out[n*Mdim+m] = acc + bias[m]                      (v conv)
// MODE 2: f32  Out[n*Mdim+m] = xres + gamma[0]*acc + gcw[b*CC+n]  (final)
// MODE 4: bf16 Out[m*Ndim+n] = acc                                (O)
// MODE 5: bf16 Out[n*Mdim+m] = acc - bias[b*PP+m]                 (q whiten)
// MODE 6: bf16 Out[m*Ndim+n] = acc - bias[b*PP+m]                 (k whiten)
// MODE 7: bf16 Out[m*Ndim+n] = acc * hscale                       (S bf16)
#define KC    64
#define LDA_  72      // 64 + 8 pad (bf16); 144B rows
#define LDBW  264     // 256 + 8 pad (bf16); 528B rows
#define LDST  264     // stage ld (f32)
#define A_ST_ELE (128*LDA_)              // bf16 elements per A stage
#define B_ST_ELE (64*LDBW)
#define A_ST_BYTES (A_ST_ELE*2)          // 18432
#define B_ST_BYTES (B_ST_ELE*2)          // 33792
#define DYN_SMEM (3*(A_ST_BYTES+B_ST_BYTES))   // 156672 (> stage 67584)

__device__ __forceinline__ void cp16(void* dst_smem, const void* src_gmem){
    unsigned int d = (unsigned int)__cvta_generic_to_shared(dst_smem);
    asm volatile("cp.async.cg.shared.global [%0], [%1], 16;\n" :: "r"(d), "l"(src_gmem));
}

template<int MODE>
__global__ void __launch_bounds__(256, 1)
gemm_kernel(const bf16* __restrict__ A, const bf16* __restrict__ Bmat,
            const float* __restrict__ bias, void* __restrict__ OutV,
            int Mdim, int Ndim, int Kdim, long sA, long sB, long sOut,
            const float* __restrict__ xres, const float* __restrict__ gcw,
            const float* __restrict__ gamma, float hscale)
{
    extern __shared__ char smraw[];
    bf16* Abuf = (bf16*)smraw;                               // [3][A_ST_ELE]
    bf16* Bbuf = (bf16*)(smraw + 3*A_ST_BYTES);              // [3][B_ST_ELE]
    float* stage = (float*)smraw;                            // epilogue reuse

    const int b = blockIdx.z;
    A    += (long)b * sA;
    Bmat += (long)b * sB;
    const int m0 = blockIdx.y * 128;
    const int n0 = blockIdx.x * 256;
    const int tid = threadIdx.x;
    const int wid = tid >> 5;
    const int warp_m = wid >> 2;      // 0..1
    const int warp_n = wid & 3;       // 0..3

    wmma::fragment<wmma::accumulator,16,16,16,float> acc[4][4];
    #pragma unroll
    for (int i=0;i<4;i++)
        #pragma unroll
        for (int j=0;j<4;j++) wmma::fill_fragment(acc[i][j], 0.f);

    auto load_tiles = [&](int st, int k0){
        #pragma unroll
        for (int p=0;p<4;p++){                               // A: 128x64 = 1024 chunks
            int ch = tid + p*256;
            int r = ch >> 3, c8 = (ch & 7)*8;
            cp16(&Abuf[st*A_ST_ELE + r*LDA_ + c8], &A[(long)(m0+r)*Kdim + k0 + c8]);
        }
        #pragma unroll
        for (int p=0;p<8;p++){                               // B: 64x256 = 2048 chunks
            int ch = tid + p*256;
            int r = ch >> 5, c8 = (ch & 31)*8;
            cp16(&Bbuf[st*B_ST_ELE + r*LDBW + c8], &Bmat[(long)(k0+r)*Ndim + n0 + c8]);
        }
    };

    const int nk = Kdim / KC;
    load_tiles(0, 0);
    asm volatile("cp.async.commit_group;\n");
    load_tiles(1, KC);
    asm volatile("cp.async.commit_group;\n");

    for (int i = 0; i < nk; i++){
        asm volatile("cp.async.wait_group 1;\n");
        __syncthreads();
        if (i + 2 < nk) load_tiles((i+2)%3, (i+2)*KC);
        asm volatile("cp.async.commit_group;\n");

        const bf16* Ab = &Abuf[(i%3)*A_ST_ELE];
        const bf16* Bb = &Bbuf[(i%3)*B_ST_ELE];
        #pragma unroll
        for (int kk=0; kk<KC; kk+=16){
            wmma::fragment<wmma::matrix_a,16,16,16,bf16,wmma::row_major> af[4];
            wmma::fragment<wmma::matrix_b,16,16,16,bf16,wmma::row_major> bfr[4];
            #pragma unroll
            for (int ii=0;ii<4;ii++)
                wmma::load_matrix_sync(af[ii], &Ab[(warp_m*64 + ii*16)*LDA_ + kk], LDA_);
            #pragma unroll
            for (int j=0;j<4;j++)
                wmma::load_matrix_sync(bfr[j], &Bb[kk*LDBW + warp_n*64 + j*16], LDBW);
            #pragma unroll
            for (int ii=0;ii<4;ii++)
                #pragma unroll
                for (int j=0;j<4;j++)
                    wmma::mma_sync(acc[ii][j], af[ii], bfr[j], acc[ii][j]);
        }
    }
    asm volatile("cp.async.wait_group 0;\n");
    __syncthreads();

    const float gmul = (MODE==2) ? gamma[0] : 0.f;
    for (int h=0; h<2; h++){
        if (warp_m == h){
            #pragma unroll
            for (int i=0;i<4;i++)
                #pragma unroll
                for (int j=0;j<4;j++)
                    wmma::store_matrix_sync(&stage[(i*16)*LDST + warp_n*64 + j*16],
                                            acc[i][j], LDST, wmma::mem_row_major);
        }
        __syncthreads();
        if (MODE == 4 || MODE == 6 || MODE == 7){
            bf16* Out = (bf16*)OutV + (long)b*sOut;
            for (int it=0; it<64; it++){
                int idx = it*256 + tid;
                int r = idx >> 8, c = idx & 255;
                int gmi = m0 + h*64 + r, gni = n0 + c;
                float v = stage[r*LDST + c];
                if (MODE == 6) v -= bias[b*PP + gmi];
                if (MODE == 7) v *= hscale;
                Out[(long)gmi*Ndim + gni] = __float2bfloat16(v);
            }
        } else if (MODE == 1 || MODE == 5){
            bf16* Out = (bf16*)OutV + (long)b*sOut;
            for (int it=0; it<64; it++){
                int idx = it*256 + tid;
                int r = idx & 63, c = idx >> 6;
                int gmi = m0 + h*64 + r, gni = n0 + c;
                float bv = (MODE==1) ? bias[gmi] : -bias[b*PP + gmi];
                Out[(long)gni*Mdim + gmi] = __float2bfloat16(stage[r*LDST + c] + bv);
            }
        } else {  // MODE 2
            float* Out = (float*)OutV + (long)b*sOut;
            const float* xr = xres + (long)b*sOut;
            for (int it=0; it<64; it++){
                int idx = it*256 + tid;
                int r = idx & 63, c = idx >> 6;
                int gmi = m0 + h*64 + r;
                int gni = n0 + c;
                long o = (long)gni*Mdim + gmi;
                Out[o] = xr[o] + gmul*stage[r*LDST + c] + gcw[b*CC + gni];
            }
        }
        __syncthreads();
    }
}

extern "C" void kernel_launch(void* const* d_in, const int* in_sizes, int n_in,
                              void* d_out, int out_size) {
    const float* x     = (const float*)d_in[0];
    const float* wq    = (const float*)d_in[1];
    const float* wk    = (const float*)d_in[3];
    const float* wv    = (const float*)d_in[5];
    const float* bv    = (const float*)d_in[6];
    const float* wgc   = (const float*)d_in[7];
    const float* bgc   = (const float*)d_in[8];
    const float* wmask = (const float*)d_in[9];
    const float* bmask = (const float*)d_in[10];
    const float* wout  = (const float*)d_in[11];
    const float* gamma = (const float*)d_in[12];
    const float* beta  = (const float*)d_in[13];

    void *p_xb, *p_ixf, *p_ixb, *p_qT, *p_k, *p_vT, *p_Sb, *p_P, *p_oT;
    void *p_wqb, *p_wkb, *p_wvb, *p_woutT, *p_mask, *p_t, *p_gc, *p_gcw;
    void *p_xsum, *p_ixsum, *p_qmn, *p_kmn;
    cudaGetSymbolAddress(&p_xb,  g_xb);
    cudaGetSymbolAddress(&p_ixf, g_ixf);
    cudaGetSymbolAddress(&p_ixb, g_ixb);
    cudaGetSymbolAddress(&p_qT,  g_qT);
    cudaGetSymbolAddress(&p_k,   g_k);
    cudaGetSymbolAddress(&p_vT,  g_vT);
    cudaGetSymbolAddress(&p_Sb,  g_Sb);
    cudaGetSymbolAddress(&p_P,   g_P);
    cudaGetSymbolAddress(&p_oT,  g_oT);
    cudaGetSymbolAddress(&p_wqb, g_wqb);
    cudaGetSymbolAddress(&p_wkb, g_wkb);
    cudaGetSymbolAddress(&p_wvb, g_wvb);
    cudaGetSymbolAddress(&p_woutT, g_woutT);
    cudaGetSymbolAddress(&p_mask, g_mask);
    cudaGetSymbolAddress(&p_t,   g_t);
    cudaGetSymbolAddress(&p_gc,  g_gc);
    cudaGetSymbolAddress(&p_gcw, g_gcw);
    cudaGetSymbolAddress(&p_xsum, g_xsum);
    cudaGetSymbolAddress(&p_ixsum, g_ixsum);
    cudaGetSymbolAddress(&p_qmn, g_qmn);
    cudaGetSymbolAddress(&p_kmn, g_kmn);

    cudaFuncSetAttribute(gemm_kernel<1>, cudaFuncAttributeMaxDynamicSharedMemorySize, DYN_SMEM);
    cudaFuncSetAttribute(gemm_kernel<2>, cudaFuncAttributeMaxDynamicSharedMemorySize, DYN_SMEM);
    cudaFuncSetAttribute(gemm_kernel<4>, cudaFuncAttributeMaxDynamicSharedMemorySize, DYN_SMEM);
    cudaFuncSetAttribute(gemm_kernel<5>, cudaFuncAttributeMaxDynamicSharedMemorySize, DYN_SMEM);
    cudaFuncSetAttribute(gemm_kernel<6>, cudaFuncAttributeMaxDynamicSharedMemorySize, DYN_SMEM);
    cudaFuncSetAttribute(gemm_kernel<7>, cudaFuncAttributeMaxDynamicSharedMemorySize, DYN_SMEM);

    const float SINV = 0.8838834764831844f;  // 1/(sqrt(512)*0.05)

    // launches: 1..3 prep, then #4..#7 are the big GEMMs
    k_f2bf<<<65536, 256>>>(x, (bf16*)p_xb, (long)BB*CC*NN/4);                       // 1
    k_pool2<<<BB*CC, 256>>>(x, (float*)p_ixf, (bf16*)p_ixb,
                            (float*)p_xsum, (float*)p_ixsum);                       // 2
    k_prep<<<dim3(512,18), 256>>>(wq, wk, wv, wout,
        (const float*)p_xsum, (const float*)p_ixsum,
        (float*)p_qmn, (float*)p_kmn,
        (bf16*)p_wqb, (bf16*)p_wkb, (bf16*)p_wvb, (bf16*)p_woutT);                  // 3

    // q = whiten(wq@x) -> qT [b][n][p]                                             // 4
    gemm_kernel<5><<<dim3(16,4,16), 256, DYN_SMEM>>>((const bf16*)p_wqb, (const bf16*)p_xb,
        (const float*)p_qmn, p_qT,
        PP, NN, CC, 0, (long)CC*NN, (long)NN*PP, nullptr, nullptr, nullptr, 0.f);

    // k = whiten(wk@ix) -> k [b][p][m]                                             // 5
    gemm_kernel<6><<<dim3(4,4,16), 256, DYN_SMEM>>>((const bf16*)p_wkb, (const bf16*)p_ixb,
        (const float*)p_kmn, p_k,
        PP, MM, CC, 0, (long)CC*MM, (long)PP*MM, nullptr, nullptr, nullptr, 0.f);

    // v = wv@ix + bv -> vT [b][m][p]                                               // 6
    gemm_kernel<1><<<dim3(4,4,16), 256, DYN_SMEM>>>((const bf16*)p_wvb, (const bf16*)p_ixb,
        bv, p_vT,
        PP, MM, CC, 0, (long)CC*MM, (long)MM*PP, nullptr, nullptr, nullptr, 0.f);

    // S = (qT @ k) * SINV -> bf16 [b][n][m]                                        // 7
    gemm_kernel<7><<<dim3(4,32,16), 256, DYN_SMEM>>>((const bf16*)p_qT, (const bf16*)p_k,
        nullptr, p_Sb,
        NN, MM, PP, (long)NN*PP, (long)PP*MM, (long)NN*MM, nullptr, nullptr, nullptr, SINV);

    // softmax -> P bf16
    k_softmax<<<BB*NN, 128>>>((const bf16*)p_Sb, (bf16*)p_P);

    // O = P @ vT -> oT bf16 [b][n][p]
    gemm_kernel<4><<<dim3(2,32,16), 256, DYN_SMEM>>>((const bf16*)p_P, (const bf16*)p_vT,
        nullptr, p_oT,
        NN, PP, MM, (long)NN*MM, (long)MM*PP, (long)NN*PP, nullptr, nullptr, nullptr, 0.f);

    // global-context branch (vgc conv eliminated: gc = wgc@(ix@mask)+bgc)
    k_masklogit<<<dim3(4,16), 256>>>((const float*)p_ixf, wmask, bmask, (float*)p_mask);
    k_masksoftmax<<<16, 256>>>((float*)p_mask);
    k_t<<<dim3(1024,16), 128>>>((const float*)p_ixf, (const float*)p_mask, (float*)p_t);
    k_gc<<<dim3(512,16), 256>>>(wgc, bgc, (const float*)p_t, (float*)p_gc);
    k_gcw<<<dim3(1024,16), 128>>>(wout, beta, (const float*)p_gc, (float*)p_gcw);

    // out[b][c][n] = x + gamma*(oT @ woutT)^T + gcw
    gemm_kernel<2><<<dim3(4,32,16), 256, DYN_SMEM>>>((const bf16*)p_oT, (const bf16*)p_woutT,
        nullptr, d_out,
        NN, CC, PP, (long)NN*PP, 0, (long)CC*NN, x, (const float*)p_gcw, gamma, 0.f);
}